// round 2
// baseline (speedup 1.0000x reference)
#include <cuda_runtime.h>
#include <math.h>
#include <stdint.h>

// ---------------------------------------------------------------------------
// SpatialHead: coordconv(256+2->64)+BN+ReLU -> offsetconv(64->18) ->
// deformconv(64->64)+BN+ReLU -> 2x [conv3x3(64->64)+BN+ReLU] -> 1x1 conv -> sigmoid
// B=8, H=W=96. Activations NHWC. GEMMs use packed fma.rn.f32x2 (FFMA2).
// ---------------------------------------------------------------------------

namespace sh {
constexpr int kB = 8, kH = 96, kW = 96;
constexpr int kPos = kB * kH * kW;          // 73728
constexpr float kEps = 1e-5f;
}

// ------------------------- scratch (__device__ globals) --------------------
__device__ __align__(16) float g_buf0[sh::kPos * 64];          // x1 / x3
__device__ __align__(16) float g_buf1[sh::kPos * 64];          // x2 / x4
__device__ __align__(16) float g_offb[sh::kPos * 18];          // offsets NHWC
__device__ __align__(16) float g_samp[(size_t)sh::kPos * 576]; // bilinear samples
__device__ __align__(16) float g_w1t[2304 * 64];               // coord conv [k][o]
__device__ __align__(16) float g_cb[sh::kH * sh::kW * 64];     // coord contribution + bias
__device__ __align__(16) float g_wofft[576 * 32];              // offset conv, padded out
__device__ __align__(16) float g_wdct[576 * 64];               // deform einsum [k][o]
__device__ __align__(16) float g_wr1t[576 * 64];
__device__ __align__(16) float g_wr2t[576 * 64];
__device__ float g_bnsc[4 * 64];
__device__ float g_bnsh[4 * 64];

// ------------------------------ helpers ------------------------------------
__device__ __forceinline__ unsigned smem_u32(const void* p) {
    unsigned a;
    asm("{ .reg .u64 t; cvta.to.shared.u64 t, %1; cvt.u32.u64 %0, t; }"
        : "=r"(a) : "l"(p));
    return a;
}
__device__ __forceinline__ unsigned long long lds64(unsigned addr) {
    unsigned long long v;
    asm volatile("ld.shared.b64 %0, [%1];" : "=l"(v) : "r"(addr));
    return v;
}
#define FMA2(d, a, b) \
    asm("fma.rn.f32x2 %0, %1, %2, %0;" : "+l"(d) : "l"(a), "l"(b))

__device__ __forceinline__ void unpack2(unsigned long long v, float& lo, float& hi) {
    asm("mov.b64 {%0, %1}, %2;" : "=f"(lo), "=f"(hi) : "l"(v));
}

// ------------------------------ prep kernel --------------------------------
__global__ void prep_kernel(
    const float* __restrict__ coord_w, const float* __restrict__ coord_b,
    const float* __restrict__ off_w, const float* __restrict__ dc_w,
    const float* __restrict__ r1_w, const float* __restrict__ r2_w,
    const float* __restrict__ bn1g, const float* __restrict__ bn1b,
    const float* __restrict__ bn1m, const float* __restrict__ bn1v,
    const float* __restrict__ bn2g, const float* __restrict__ bn2b,
    const float* __restrict__ bn2m, const float* __restrict__ bn2v,
    const float* __restrict__ bn3g, const float* __restrict__ bn3b,
    const float* __restrict__ bn3m, const float* __restrict__ bn3v,
    const float* __restrict__ bn4g, const float* __restrict__ bn4b,
    const float* __restrict__ bn4m, const float* __restrict__ bn4v)
{
    int idx = blockIdx.x * blockDim.x + threadIdx.x;
    const int N1 = 2304 * 64;
    const int N2 = sh::kH * sh::kW * 64;
    const int N3 = 576 * 32;
    const int N4 = 576 * 64;

    if (idx < N1) {
        int o = idx & 63, k = idx >> 6;
        int t = k >> 8, c = k & 255;
        g_w1t[idx] = coord_w[(o * 258 + c) * 9 + t];
        return;
    }
    idx -= N1;
    if (idx < N2) {
        int o = idx & 63, p = idx >> 6;
        int y = p / 96, x = p % 96;
        float acc = coord_b[o];
        #pragma unroll
        for (int t = 0; t < 9; t++) {
            int yy = y + t / 3 - 1, xx = x + t % 3 - 1;
            if ((unsigned)yy < 96u && (unsigned)xx < 96u) {
                float xv = fmaf((float)xx, 2.0f / 95.0f, -1.0f);
                float yv = fmaf((float)yy, 2.0f / 95.0f, -1.0f);
                acc = fmaf(coord_w[(o * 258 + 256) * 9 + t], xv, acc);
                acc = fmaf(coord_w[(o * 258 + 257) * 9 + t], yv, acc);
            }
        }
        g_cb[p * 64 + o] = acc;
        return;
    }
    idx -= N2;
    if (idx < N3) {
        int o = idx & 31, k = idx >> 5;
        int t = k >> 6, c = k & 63;
        g_wofft[idx] = (o < 18) ? off_w[(o * 64 + c) * 9 + t] : 0.0f;
        return;
    }
    idx -= N3;
    if (idx < N4) {
        int o = idx & 63, k = idx >> 6;
        int t = k >> 6, c = k & 63;
        g_wdct[idx] = dc_w[(o * 64 + c) * 9 + t];
        return;
    }
    idx -= N4;
    if (idx < N4) {
        int o = idx & 63, k = idx >> 6;
        int t = k >> 6, c = k & 63;
        g_wr1t[idx] = r1_w[(o * 64 + c) * 9 + t];
        return;
    }
    idx -= N4;
    if (idx < N4) {
        int o = idx & 63, k = idx >> 6;
        int t = k >> 6, c = k & 63;
        g_wr2t[idx] = r2_w[(o * 64 + c) * 9 + t];
        return;
    }
    idx -= N4;
    if (idx < 512) {
        int which = idx >> 7, r = idx & 127, o = r & 63;
        const float* gs; const float* bs; const float* ms; const float* vs;
        if (which == 0)      { gs = bn1g; bs = bn1b; ms = bn1m; vs = bn1v; }
        else if (which == 1) { gs = bn2g; bs = bn2b; ms = bn2m; vs = bn2v; }
        else if (which == 2) { gs = bn3g; bs = bn3b; ms = bn3m; vs = bn3v; }
        else                 { gs = bn4g; bs = bn4b; ms = bn4m; vs = bn4v; }
        float sc = gs[o] * rsqrtf(vs[o] + sh::kEps);
        if (r < 64) g_bnsc[which * 64 + o] = sc;
        else        g_bnsh[which * 64 + o] = bs[o] - ms[o] * sc;
    }
}

// ------------------------------ conv GEMM (FFMA2) ---------------------------
// Block: 64 positions (2 rows x 32 cols) x BN output channels, 4*BN threads.
// Micro-tile 4 pos x 4 ch per thread, accumulators packed f32x2 over position
// pairs. B tile stored duplicated (w,w) so both operands are single LDS.64.
// MODE 0: + per-position bias + BN + ReLU   (coord conv)
// MODE 1: + channel bias, store 18 channels (offset conv)
// MODE 2: + BN + ReLU                       (deform / r1 / r2)
template <int CIN, int TAPS, int BN, int MODE>
__global__ void __launch_bounds__(4 * BN)
conv_gemm(const float* __restrict__ in, const float* __restrict__ wT,
          const float* __restrict__ posbias, const float* __restrict__ chbias,
          const float* __restrict__ bnsc, const float* __restrict__ bnsh,
          float* __restrict__ out)
{
    constexpr int CPT = CIN / 32;
    constexpr int KCH = TAPS * CPT;
    constexpr int AROW = 68;            // 64 pos + pad
    constexpr int BROW = 2 * BN + 4;    // duplicated + pad
    __shared__ float sA[32][AROW];
    __shared__ float sBd[32][BROW];

    const int tid = threadIdx.x;
    const int x0 = blockIdx.x * 32;
    const int ybase = blockIdx.y * 2;
    const int b = blockIdx.z;

    const int pg = tid & 15;            // position group (x4)
    const int cg = tid >> 4;            // channel group (x4), 0..BN/4-1

    const unsigned aAddr = smem_u32(&sA[0][0]) + pg * 16;
    const unsigned bAddr = smem_u32(&sBd[0][0]) + cg * 32;

    unsigned long long acc[2][4];
    #pragma unroll
    for (int i = 0; i < 2; i++)
        #pragma unroll
        for (int j = 0; j < 4; j++) acc[i][j] = 0ull;

    for (int ch = 0; ch < KCH; ch++) {
        const int t = (TAPS == 1) ? 0 : (ch / CPT);
        const int c0 = (ch % CPT) * 32;
        const int dy = (TAPS == 1) ? 0 : (t / 3 - 1);
        const int dx = (TAPS == 1) ? 0 : (t % 3 - 1);

        // ---- fill A: 64 pos x 32 ch, transposed [c][pos] ----
        if constexpr (BN == 64) {       // 256 threads: 8 floats each
            const int i = tid >> 2;
            const int cb4 = (tid & 3) * 8;
            const int yy = ybase + (i >> 5) + dy;
            const int xx = x0 + (i & 31) + dx;
            float4 v0 = make_float4(0.f, 0.f, 0.f, 0.f), v1 = v0;
            if (TAPS == 1 || ((unsigned)yy < (unsigned)sh::kH &&
                              (unsigned)xx < (unsigned)sh::kW)) {
                const float* src = in + (size_t)((b * sh::kH + yy) * sh::kW + xx) * CIN + c0 + cb4;
                v0 = ((const float4*)src)[0];
                v1 = ((const float4*)src)[1];
            }
            sA[cb4 + 0][i] = v0.x; sA[cb4 + 1][i] = v0.y;
            sA[cb4 + 2][i] = v0.z; sA[cb4 + 3][i] = v0.w;
            sA[cb4 + 4][i] = v1.x; sA[cb4 + 5][i] = v1.y;
            sA[cb4 + 6][i] = v1.z; sA[cb4 + 7][i] = v1.w;
        } else {                        // 128 threads: 16 floats each
            const int i = tid >> 1;
            const int cb4 = (tid & 1) * 16;
            const int yy = ybase + (i >> 5) + dy;
            const int xx = x0 + (i & 31) + dx;
            float4 v[4];
            if (TAPS == 1 || ((unsigned)yy < (unsigned)sh::kH &&
                              (unsigned)xx < (unsigned)sh::kW)) {
                const float* src = in + (size_t)((b * sh::kH + yy) * sh::kW + xx) * CIN + c0 + cb4;
                v[0] = ((const float4*)src)[0]; v[1] = ((const float4*)src)[1];
                v[2] = ((const float4*)src)[2]; v[3] = ((const float4*)src)[3];
            } else {
                v[0] = v[1] = v[2] = v[3] = make_float4(0.f, 0.f, 0.f, 0.f);
            }
            #pragma unroll
            for (int q = 0; q < 4; q++) {
                sA[cb4 + q * 4 + 0][i] = v[q].x;
                sA[cb4 + q * 4 + 1][i] = v[q].y;
                sA[cb4 + q * 4 + 2][i] = v[q].z;
                sA[cb4 + q * 4 + 3][i] = v[q].w;
            }
        }

        // ---- fill B duplicated: 32 k x BN -> [k][(w,w) pairs] ----
        {
            constexpr int GRP = BN / 8;          // threads per row
            const int r = tid / GRP;             // 0..31
            const int cs = (tid % GRP) * 8;
            const float* ws = wT + (size_t)(ch * 32 + r) * BN + cs;
            float4 w0 = ((const float4*)ws)[0];
            float4 w1 = ((const float4*)ws)[1];
            float4* dst = (float4*)&sBd[r][2 * cs];
            dst[0] = make_float4(w0.x, w0.x, w0.y, w0.y);
            dst[1] = make_float4(w0.z, w0.z, w0.w, w0.w);
            dst[2] = make_float4(w1.x, w1.x, w1.y, w1.y);
            dst[3] = make_float4(w1.z, w1.z, w1.w, w1.w);
        }
        __syncthreads();

        // ---- inner product: 6 LDS.64 + 8 FMA2 per k ----
        #pragma unroll
        for (int k = 0; k < 32; k++) {
            const unsigned ak = aAddr + k * (AROW * 4);
            const unsigned bk = bAddr + k * (BROW * 4);
            unsigned long long a01 = lds64(ak);
            unsigned long long a23 = lds64(ak + 8);
            unsigned long long b0 = lds64(bk);
            unsigned long long b1 = lds64(bk + 8);
            unsigned long long b2 = lds64(bk + 16);
            unsigned long long b3 = lds64(bk + 24);
            FMA2(acc[0][0], a01, b0);
            FMA2(acc[0][1], a01, b1);
            FMA2(acc[0][2], a01, b2);
            FMA2(acc[0][3], a01, b3);
            FMA2(acc[1][0], a23, b0);
            FMA2(acc[1][1], a23, b1);
            FMA2(acc[1][2], a23, b2);
            FMA2(acc[1][3], a23, b3);
        }
        __syncthreads();
    }

    // ---- unpack accumulators: v[ii][j], ii = pos offset 0..3 ----
    float v[4][4];
    #pragma unroll
    for (int pi = 0; pi < 2; pi++)
        #pragma unroll
        for (int j = 0; j < 4; j++)
            unpack2(acc[pi][j], v[2 * pi][j], v[2 * pi + 1][j]);

    float4 sc4, sh4;
    if constexpr (MODE != 1) {
        sc4 = ((const float4*)bnsc)[cg];
        sh4 = ((const float4*)bnsh)[cg];
    }

    #pragma unroll
    for (int ii = 0; ii < 4; ii++) {
        const int p = pg * 4 + ii;
        const int py = ybase + (p >> 5);
        const int px = x0 + (p & 31);
        const int pos = (b * sh::kH + py) * sh::kW + px;
        if constexpr (MODE == 0) {
            float4 pb = *(const float4*)&posbias[(size_t)(py * sh::kW + px) * 64 + cg * 4];
            float4 r;
            r.x = fmaxf(fmaf(v[ii][0] + pb.x, sc4.x, sh4.x), 0.0f);
            r.y = fmaxf(fmaf(v[ii][1] + pb.y, sc4.y, sh4.y), 0.0f);
            r.z = fmaxf(fmaf(v[ii][2] + pb.z, sc4.z, sh4.z), 0.0f);
            r.w = fmaxf(fmaf(v[ii][3] + pb.w, sc4.w, sh4.w), 0.0f);
            *(float4*)&out[(size_t)pos * 64 + cg * 4] = r;
        } else if constexpr (MODE == 1) {
            #pragma unroll
            for (int j = 0; j < 4; j++) {
                const int o = cg * 4 + j;
                if (o < 18) out[(size_t)pos * 18 + o] = v[ii][j] + chbias[o];
            }
        } else {
            float4 r;
            r.x = fmaxf(fmaf(v[ii][0], sc4.x, sh4.x), 0.0f);
            r.y = fmaxf(fmaf(v[ii][1], sc4.y, sh4.y), 0.0f);
            r.z = fmaxf(fmaf(v[ii][2], sc4.z, sh4.z), 0.0f);
            r.w = fmaxf(fmaf(v[ii][3], sc4.w, sh4.w), 0.0f);
            *(float4*)&out[(size_t)pos * 64 + cg * 4] = r;
        }
    }
}

// --------------------------- deform sampling -------------------------------
__device__ __forceinline__ void corner_acc(const float4* __restrict__ base,
                                           int yy, int xx, int cq, float w,
                                           float4& acc)
{
    if ((unsigned)yy < 96u && (unsigned)xx < 96u) {
        float4 vv = base[(yy * 96 + xx) * 16 + cq];
        acc.x = fmaf(w, vv.x, acc.x);
        acc.y = fmaf(w, vv.y, acc.y);
        acc.z = fmaf(w, vv.z, acc.z);
        acc.w = fmaf(w, vv.w, acc.w);
    }
}

__global__ void sample_kernel(const float* __restrict__ x1,
                              const float* __restrict__ offs,
                              float* __restrict__ samp)
{
    int gid = blockIdx.x * blockDim.x + threadIdx.x;   // kPos * 16
    if (gid >= sh::kPos * 16) return;
    const int cq = gid & 15;
    const int pos = gid >> 4;
    const int b = pos / (sh::kH * sh::kW);
    const int rem = pos % (sh::kH * sh::kW);
    const int y = rem / sh::kW, x = rem % sh::kW;

    const float* op = offs + (size_t)pos * 18;
    const float4* base = (const float4*)x1 + (size_t)(b * sh::kH * sh::kW) * 16;
    float4* outp = (float4*)(samp + (size_t)pos * 576);

    #pragma unroll
    for (int t = 0; t < 9; t++) {
        float oy = op[2 * t];
        float ox = op[2 * t + 1];
        float py = (float)(y + t / 3 - 1) + oy;
        float px = (float)(x + t % 3 - 1) + ox;
        float y0f = floorf(py), x0f = floorf(px);
        float fy = py - y0f, fx = px - x0f;
        int y0 = (int)y0f, xx0 = (int)x0f;
        float w00 = (1.0f - fy) * (1.0f - fx);
        float w01 = (1.0f - fy) * fx;
        float w10 = fy * (1.0f - fx);
        float w11 = fy * fx;
        float4 acc = make_float4(0.f, 0.f, 0.f, 0.f);
        corner_acc(base, y0,     xx0,     cq, w00, acc);
        corner_acc(base, y0,     xx0 + 1, cq, w01, acc);
        corner_acc(base, y0 + 1, xx0,     cq, w10, acc);
        corner_acc(base, y0 + 1, xx0 + 1, cq, w11, acc);
        outp[t * 16 + cq] = acc;
    }
}

// ------------------------------ final 1x1 ----------------------------------
__global__ void final_kernel(const float* __restrict__ x4,
                             const float* __restrict__ ow,
                             const float* __restrict__ ob,
                             float* __restrict__ out)
{
    int pos = blockIdx.x * blockDim.x + threadIdx.x;
    if (pos >= sh::kPos) return;
    const float4* xr = (const float4*)(x4 + (size_t)pos * 64);
    const float4* wr = (const float4*)ow;
    float acc = ob[0];
    #pragma unroll
    for (int q = 0; q < 16; q++) {
        float4 a = xr[q], w = wr[q];
        acc = fmaf(a.x, w.x, acc);
        acc = fmaf(a.y, w.y, acc);
        acc = fmaf(a.z, w.z, acc);
        acc = fmaf(a.w, w.w, acc);
    }
    out[pos] = 1.0f / (1.0f + expf(-acc));
}

// ------------------------------ launcher -----------------------------------
extern "C" void kernel_launch(void* const* d_in, const int* in_sizes, int n_in,
                              void* d_out, int out_size)
{
    const float* features = (const float*)d_in[0];
    const float* coord_w  = (const float*)d_in[1];
    const float* coord_b  = (const float*)d_in[2];
    const float* bn1g = (const float*)d_in[3];
    const float* bn1b = (const float*)d_in[4];
    const float* bn1m = (const float*)d_in[5];
    const float* bn1v = (const float*)d_in[6];
    const float* off_w = (const float*)d_in[7];
    const float* off_b = (const float*)d_in[8];
    const float* dc_w  = (const float*)d_in[9];
    const float* bn2g = (const float*)d_in[10];
    const float* bn2b = (const float*)d_in[11];
    const float* bn2m = (const float*)d_in[12];
    const float* bn2v = (const float*)d_in[13];
    const float* r1_w = (const float*)d_in[14];
    const float* bn3g = (const float*)d_in[15];
    const float* bn3b = (const float*)d_in[16];
    const float* bn3m = (const float*)d_in[17];
    const float* bn3v = (const float*)d_in[18];
    const float* r2_w = (const float*)d_in[19];
    const float* bn4g = (const float*)d_in[20];
    const float* bn4b = (const float*)d_in[21];
    const float* bn4m = (const float*)d_in[22];
    const float* bn4v = (const float*)d_in[23];
    const float* out_w = (const float*)d_in[24];
    const float* out_b = (const float*)d_in[25];

    float *p_buf0, *p_buf1, *p_off, *p_samp, *p_w1t, *p_cb, *p_wofft,
          *p_wdct, *p_wr1t, *p_wr2t, *p_bnsc, *p_bnsh;
    cudaGetSymbolAddress((void**)&p_buf0, g_buf0);
    cudaGetSymbolAddress((void**)&p_buf1, g_buf1);
    cudaGetSymbolAddress((void**)&p_off,  g_offb);
    cudaGetSymbolAddress((void**)&p_samp, g_samp);
    cudaGetSymbolAddress((void**)&p_w1t,  g_w1t);
    cudaGetSymbolAddress((void**)&p_cb,   g_cb);
    cudaGetSymbolAddress((void**)&p_wofft, g_wofft);
    cudaGetSymbolAddress((void**)&p_wdct, g_wdct);
    cudaGetSymbolAddress((void**)&p_wr1t, g_wr1t);
    cudaGetSymbolAddress((void**)&p_wr2t, g_wr2t);
    cudaGetSymbolAddress((void**)&p_bnsc, g_bnsc);
    cudaGetSymbolAddress((void**)&p_bnsh, g_bnsh);

    // 1. prep
    const int prep_total = 2304 * 64 + 96 * 96 * 64 + 576 * 32 + 3 * 576 * 64 + 512;
    prep_kernel<<<(prep_total + 255) / 256, 256>>>(
        coord_w, coord_b, off_w, dc_w, r1_w, r2_w,
        bn1g, bn1b, bn1m, bn1v, bn2g, bn2b, bn2m, bn2v,
        bn3g, bn3b, bn3m, bn3v, bn4g, bn4b, bn4m, bn4v);

    dim3 grid(3, 48, 8);   // 32 x-cols, 2 rows per block

    // 2. coord conv (256->64) + coord bias + BN1 + ReLU -> buf0
    conv_gemm<256, 9, 64, 0><<<grid, 256>>>(
        features, p_w1t, p_cb, nullptr, p_bnsc + 0, p_bnsh + 0, p_buf0);

    // 3. offset conv (64->18) + bias -> g_offb
    conv_gemm<64, 9, 32, 1><<<grid, 128>>>(
        p_buf0, p_wofft, nullptr, off_b, nullptr, nullptr, p_off);

    // 4. deform bilinear sampling -> g_samp
    sample_kernel<<<(sh::kPos * 16 + 255) / 256, 256>>>(p_buf0, p_off, p_samp);

    // 5. deform einsum (K=576) + BN2 + ReLU -> buf1
    conv_gemm<576, 1, 64, 2><<<grid, 256>>>(
        p_samp, p_wdct, nullptr, nullptr, p_bnsc + 64, p_bnsh + 64, p_buf1);

    // 6. r1 conv + BN3 + ReLU -> buf0
    conv_gemm<64, 9, 64, 2><<<grid, 256>>>(
        p_buf1, p_wr1t, nullptr, nullptr, p_bnsc + 128, p_bnsh + 128, p_buf0);

    // 7. r2 conv + BN4 + ReLU -> buf1
    conv_gemm<64, 9, 64, 2><<<grid, 256>>>(
        p_buf0, p_wr2t, nullptr, nullptr, p_bnsc + 192, p_bnsh + 192, p_buf1);

    // 8. 1x1 conv + sigmoid -> d_out
    final_kernel<<<(sh::kPos + 255) / 256, 256>>>(
        p_buf1, out_w, out_b, (float*)d_out);
}

// round 3
// speedup vs baseline: 2.6517x; 2.6517x over previous
#include <cuda_runtime.h>
#include <math.h>
#include <stdint.h>

// ---------------------------------------------------------------------------
// SpatialHead on sm_103a — tensor-core TF32 implicit-GEMM version.
// coordconv(256+2->64)+BN+ReLU -> offsetconv(64->18) -> deformconv(64->64)
// +BN+ReLU -> 2x [conv3x3(64->64)+BN+ReLU] -> 1x1 conv -> sigmoid
// B=8, H=W=96. Activations NHWC fp32; GEMMs via mma.sync tf32 (fp32 accum).
// ---------------------------------------------------------------------------

namespace sh {
constexpr int kB = 8, kH = 96, kW = 96;
constexpr int kPos = kB * kH * kW;          // 73728
constexpr float kEps = 1e-5f;
}

// ------------------------- scratch (__device__ globals) --------------------
__device__ __align__(16) float g_buf0[sh::kPos * 64];          // x1 / x3
__device__ __align__(16) float g_buf1[sh::kPos * 64];          // x2 / x4
__device__ __align__(16) float g_offb[sh::kPos * 18];          // offsets NHWC
__device__ __align__(16) float g_samp[(size_t)sh::kPos * 576]; // bilinear samples
__device__ __align__(16) float g_w1t[2304 * 64];               // coord conv [k][o] tf32
__device__ __align__(16) float g_cb[sh::kH * sh::kW * 64];     // coord contribution + bias (fp32)
__device__ __align__(16) float g_wofft[576 * 64];              // offset conv, padded to 64 out, tf32
__device__ __align__(16) float g_wdct[576 * 64];               // deform einsum [k][o] tf32
__device__ __align__(16) float g_wr1t[576 * 64];
__device__ __align__(16) float g_wr2t[576 * 64];
__device__ float g_bnsc[4 * 64];
__device__ float g_bnsh[4 * 64];

// ------------------------------ helpers ------------------------------------
__device__ __forceinline__ float f2tf32(float x) {
    uint32_t r;
    asm("cvt.rna.tf32.f32 %0, %1;" : "=r"(r) : "f"(x));
    return __uint_as_float(r);
}

__device__ __forceinline__ void mma_tf32(float c[4], const uint32_t a[4],
                                         uint32_t b0, uint32_t b1) {
    asm volatile(
        "mma.sync.aligned.m16n8k8.row.col.f32.tf32.tf32.f32 "
        "{%0,%1,%2,%3}, {%4,%5,%6,%7}, {%8,%9}, {%0,%1,%2,%3};\n"
        : "+f"(c[0]), "+f"(c[1]), "+f"(c[2]), "+f"(c[3])
        : "r"(a[0]), "r"(a[1]), "r"(a[2]), "r"(a[3]), "r"(b0), "r"(b1));
}

// ------------------------------ prep kernel --------------------------------
// Repacks weights to [k][o] layout (pre-truncated to TF32), precomputes the
// coord-channel bias map (fp32) and folded BN scale/shift.
__global__ void prep_kernel(
    const float* __restrict__ coord_w, const float* __restrict__ coord_b,
    const float* __restrict__ off_w, const float* __restrict__ dc_w,
    const float* __restrict__ r1_w, const float* __restrict__ r2_w,
    const float* __restrict__ bn1g, const float* __restrict__ bn1b,
    const float* __restrict__ bn1m, const float* __restrict__ bn1v,
    const float* __restrict__ bn2g, const float* __restrict__ bn2b,
    const float* __restrict__ bn2m, const float* __restrict__ bn2v,
    const float* __restrict__ bn3g, const float* __restrict__ bn3b,
    const float* __restrict__ bn3m, const float* __restrict__ bn3v,
    const float* __restrict__ bn4g, const float* __restrict__ bn4b,
    const float* __restrict__ bn4m, const float* __restrict__ bn4v)
{
    int idx = blockIdx.x * blockDim.x + threadIdx.x;
    const int N1 = 2304 * 64;
    const int N2 = sh::kH * sh::kW * 64;
    const int N3 = 576 * 64;

    if (idx < N1) {
        int o = idx & 63, k = idx >> 6;
        int t = k >> 8, c = k & 255;
        g_w1t[idx] = f2tf32(coord_w[(o * 258 + c) * 9 + t]);
        return;
    }
    idx -= N1;
    if (idx < N2) {
        int o = idx & 63, p = idx >> 6;
        int y = p / 96, x = p % 96;
        float acc = coord_b[o];
        #pragma unroll
        for (int t = 0; t < 9; t++) {
            int yy = y + t / 3 - 1, xx = x + t % 3 - 1;
            if ((unsigned)yy < 96u && (unsigned)xx < 96u) {
                float xv = fmaf((float)xx, 2.0f / 95.0f, -1.0f);
                float yv = fmaf((float)yy, 2.0f / 95.0f, -1.0f);
                acc = fmaf(coord_w[(o * 258 + 256) * 9 + t], xv, acc);
                acc = fmaf(coord_w[(o * 258 + 257) * 9 + t], yv, acc);
            }
        }
        g_cb[p * 64 + o] = acc;
        return;
    }
    idx -= N2;
    if (idx < N3) {   // offset conv padded to 64 outputs
        int o = idx & 63, k = idx >> 6;
        int t = k >> 6, c = k & 63;
        g_wofft[idx] = (o < 18) ? f2tf32(off_w[(o * 64 + c) * 9 + t]) : 0.0f;
        return;
    }
    idx -= N3;
    if (idx < N3) {
        int o = idx & 63, k = idx >> 6;
        int t = k >> 6, c = k & 63;
        g_wdct[idx] = f2tf32(dc_w[(o * 64 + c) * 9 + t]);
        return;
    }
    idx -= N3;
    if (idx < N3) {
        int o = idx & 63, k = idx >> 6;
        int t = k >> 6, c = k & 63;
        g_wr1t[idx] = f2tf32(r1_w[(o * 64 + c) * 9 + t]);
        return;
    }
    idx -= N3;
    if (idx < N3) {
        int o = idx & 63, k = idx >> 6;
        int t = k >> 6, c = k & 63;
        g_wr2t[idx] = f2tf32(r2_w[(o * 64 + c) * 9 + t]);
        return;
    }
    idx -= N3;
    if (idx < 512) {
        int which = idx >> 7, r = idx & 127, o = r & 63;
        const float* gs; const float* bs; const float* ms; const float* vs;
        if (which == 0)      { gs = bn1g; bs = bn1b; ms = bn1m; vs = bn1v; }
        else if (which == 1) { gs = bn2g; bs = bn2b; ms = bn2m; vs = bn2v; }
        else if (which == 2) { gs = bn3g; bs = bn3b; ms = bn3m; vs = bn3v; }
        else                 { gs = bn4g; bs = bn4b; ms = bn4m; vs = bn4v; }
        float sc = gs[o] * rsqrtf(vs[o] + sh::kEps);
        if (r < 64) g_bnsc[which * 64 + o] = sc;
        else        g_bnsh[which * 64 + o] = bs[o] - ms[o] * sc;
    }
}

// --------------------------- conv GEMM (mma.sync tf32) ---------------------
// Block: 128 positions (4 rows x 32 cols) x 64 cout. 8 warps (256 threads).
// Warp grid 4(M) x 2(N): warp tile m32 x n32 = 2x4 mma.m16n8k8 tiles.
// smem: sA [k=32][m=128] pitch 136 (8 mod 32 -> conflict-free fragment LDS),
//       sB [k=32][n=64]  pitch 72.
// MODE 0: + per-position bias + BN + ReLU   (coord conv)
// MODE 1: + channel bias, store 18 channels (offset conv)
// MODE 2: + BN + ReLU                       (deform / r1 / r2)
template <int CIN, int TAPS, int MODE>
__global__ void __launch_bounds__(256)
conv_mma(const float* __restrict__ in, const float* __restrict__ wT,
         const float* __restrict__ posbias, const float* __restrict__ chbias,
         const float* __restrict__ bnsc, const float* __restrict__ bnsh,
         float* __restrict__ out)
{
    constexpr int CPT = CIN / 32;
    constexpr int KCH = TAPS * CPT;
    constexpr int AROW = 136;
    constexpr int BROW = 72;
    __shared__ float sA[32][AROW];
    __shared__ float sB[32][BROW];

    const int tid = threadIdx.x;
    const int wid = tid >> 5;
    const int lane = tid & 31;
    const int warpM = wid & 3;           // 0..3 -> m32 each
    const int warpN = wid >> 2;          // 0..1 -> n32 each
    const int g = lane >> 2;             // 0..7
    const int tg = lane & 3;             // 0..3

    const int x0 = blockIdx.x * 32;
    const int ybase = blockIdx.y * 4;
    const int b = blockIdx.z;

    float c[2][4][4];
    #pragma unroll
    for (int mt = 0; mt < 2; mt++)
        #pragma unroll
        for (int nt = 0; nt < 4; nt++)
            #pragma unroll
            for (int r = 0; r < 4; r++) c[mt][nt][r] = 0.0f;

    for (int ch = 0; ch < KCH; ch++) {
        const int t = (TAPS == 1) ? 0 : (ch / CPT);
        const int c0 = (ch % CPT) * 32;
        const int dy = (TAPS == 1) ? 0 : (t / 3 - 1);
        const int dx = (TAPS == 1) ? 0 : (t % 3 - 1);

        // ---- fill A: 128 pos x 32 ch, transposed [c][pos], tf32-truncated --
        {
            const int i = tid >> 1;            // position 0..127
            const int cb = (tid & 1) * 16;     // channel base
            const int yy = ybase + (i >> 5) + dy;
            const int xx = x0 + (i & 31) + dx;
            float4 v[4];
            if (TAPS == 1 || ((unsigned)yy < 96u && (unsigned)xx < 96u)) {
                const float* src = in + (size_t)((b * 96 + yy) * 96 + xx) * CIN + c0 + cb;
                v[0] = ((const float4*)src)[0]; v[1] = ((const float4*)src)[1];
                v[2] = ((const float4*)src)[2]; v[3] = ((const float4*)src)[3];
            } else {
                v[0] = v[1] = v[2] = v[3] = make_float4(0.f, 0.f, 0.f, 0.f);
            }
            #pragma unroll
            for (int q = 0; q < 4; q++) {
                sA[cb + q * 4 + 0][i] = f2tf32(v[q].x);
                sA[cb + q * 4 + 1][i] = f2tf32(v[q].y);
                sA[cb + q * 4 + 2][i] = f2tf32(v[q].z);
                sA[cb + q * 4 + 3][i] = f2tf32(v[q].w);
            }
        }
        // ---- fill B: 32 k x 64 n (already tf32 in gmem) --------------------
        {
            const int r = tid >> 3;            // 0..31
            const int cs = (tid & 7) * 8;      // 0..56
            const float* ws = wT + (size_t)(ch * 32 + r) * 64 + cs;
            *(float4*)&sB[r][cs]     = ((const float4*)ws)[0];
            *(float4*)&sB[r][cs + 4] = ((const float4*)ws)[1];
        }
        __syncthreads();

        // ---- 4 k-steps of 8 ------------------------------------------------
        #pragma unroll
        for (int ks = 0; ks < 4; ks++) {
            const int k0 = ks * 8;
            uint32_t a[2][4];
            #pragma unroll
            for (int mt = 0; mt < 2; mt++) {
                const int m0 = warpM * 32 + mt * 16;
                a[mt][0] = __float_as_uint(sA[k0 + tg][m0 + g]);
                a[mt][1] = __float_as_uint(sA[k0 + tg][m0 + g + 8]);
                a[mt][2] = __float_as_uint(sA[k0 + tg + 4][m0 + g]);
                a[mt][3] = __float_as_uint(sA[k0 + tg + 4][m0 + g + 8]);
            }
            #pragma unroll
            for (int nt = 0; nt < 4; nt++) {
                const int n0 = warpN * 32 + nt * 8;
                uint32_t b0 = __float_as_uint(sB[k0 + tg][n0 + g]);
                uint32_t b1 = __float_as_uint(sB[k0 + tg + 4][n0 + g]);
                mma_tf32(c[0][nt], a[0], b0, b1);
                mma_tf32(c[1][nt], a[1], b0, b1);
            }
        }
        __syncthreads();
    }

    // ------------------------------- epilogue -------------------------------
    #pragma unroll
    for (int mt = 0; mt < 2; mt++) {
        #pragma unroll
        for (int rr = 0; rr < 2; rr++) {
            const int m = warpM * 32 + mt * 16 + rr * 8 + g;
            const int py = ybase + (m >> 5);
            const int px = x0 + (m & 31);
            const size_t pos = ((size_t)b * 96 + py) * 96 + px;
            #pragma unroll
            for (int nt = 0; nt < 4; nt++) {
                const int o = warpN * 32 + nt * 8 + tg * 2;
                float v0 = c[mt][nt][rr * 2 + 0];
                float v1 = c[mt][nt][rr * 2 + 1];
                if constexpr (MODE == 0) {
                    const float2 pb = *(const float2*)&posbias[(size_t)(py * 96 + px) * 64 + o];
                    v0 += pb.x; v1 += pb.y;
                    const float2 sc = *(const float2*)&bnsc[o];
                    const float2 shb = *(const float2*)&bnsh[o];
                    v0 = fmaxf(fmaf(v0, sc.x, shb.x), 0.0f);
                    v1 = fmaxf(fmaf(v1, sc.y, shb.y), 0.0f);
                    *(float2*)&out[pos * 64 + o] = make_float2(v0, v1);
                } else if constexpr (MODE == 1) {
                    if (o < 18)     out[pos * 18 + o]     = v0 + chbias[o];
                    if (o + 1 < 18) out[pos * 18 + o + 1] = v1 + chbias[o + 1];
                } else {
                    const float2 sc = *(const float2*)&bnsc[o];
                    const float2 shb = *(const float2*)&bnsh[o];
                    v0 = fmaxf(fmaf(v0, sc.x, shb.x), 0.0f);
                    v1 = fmaxf(fmaf(v1, sc.y, shb.y), 0.0f);
                    *(float2*)&out[pos * 64 + o] = make_float2(v0, v1);
                }
            }
        }
    }
}

// --------------------------- deform sampling -------------------------------
__device__ __forceinline__ void corner_acc(const float4* __restrict__ base,
                                           int yy, int xx, int cq, float w,
                                           float4& acc)
{
    if ((unsigned)yy < 96u && (unsigned)xx < 96u) {
        float4 vv = base[(yy * 96 + xx) * 16 + cq];
        acc.x = fmaf(w, vv.x, acc.x);
        acc.y = fmaf(w, vv.y, acc.y);
        acc.z = fmaf(w, vv.z, acc.z);
        acc.w = fmaf(w, vv.w, acc.w);
    }
}

__global__ void sample_kernel(const float* __restrict__ x1,
                              const float* __restrict__ offs,
                              float* __restrict__ samp)
{
    int gid = blockIdx.x * blockDim.x + threadIdx.x;   // kPos * 16
    if (gid >= sh::kPos * 16) return;
    const int cq = gid & 15;
    const int pos = gid >> 4;
    const int b = pos / (sh::kH * sh::kW);
    const int rem = pos % (sh::kH * sh::kW);
    const int y = rem / sh::kW, x = rem % sh::kW;

    const float* op = offs + (size_t)pos * 18;
    const float4* base = (const float4*)x1 + (size_t)(b * sh::kH * sh::kW) * 16;
    float4* outp = (float4*)(samp + (size_t)pos * 576);

    #pragma unroll
    for (int t = 0; t < 9; t++) {
        float oy = op[2 * t];
        float ox = op[2 * t + 1];
        float py = (float)(y + t / 3 - 1) + oy;
        float px = (float)(x + t % 3 - 1) + ox;
        float y0f = floorf(py), x0f = floorf(px);
        float fy = py - y0f, fx = px - x0f;
        int y0 = (int)y0f, xx0 = (int)x0f;
        float w00 = (1.0f - fy) * (1.0f - fx);
        float w01 = (1.0f - fy) * fx;
        float w10 = fy * (1.0f - fx);
        float w11 = fy * fx;
        float4 acc = make_float4(0.f, 0.f, 0.f, 0.f);
        corner_acc(base, y0,     xx0,     cq, w00, acc);
        corner_acc(base, y0,     xx0 + 1, cq, w01, acc);
        corner_acc(base, y0 + 1, xx0,     cq, w10, acc);
        corner_acc(base, y0 + 1, xx0 + 1, cq, w11, acc);
        outp[t * 16 + cq] = acc;
    }
}

// ------------------------------ final 1x1 ----------------------------------
__global__ void final_kernel(const float* __restrict__ x4,
                             const float* __restrict__ ow,
                             const float* __restrict__ ob,
                             float* __restrict__ out)
{
    int pos = blockIdx.x * blockDim.x + threadIdx.x;
    if (pos >= sh::kPos) return;
    const float4* xr = (const float4*)(x4 + (size_t)pos * 64);
    const float4* wr = (const float4*)ow;
    float acc = ob[0];
    #pragma unroll
    for (int q = 0; q < 16; q++) {
        float4 a = xr[q], w = wr[q];
        acc = fmaf(a.x, w.x, acc);
        acc = fmaf(a.y, w.y, acc);
        acc = fmaf(a.z, w.z, acc);
        acc = fmaf(a.w, w.w, acc);
    }
    out[pos] = 1.0f / (1.0f + expf(-acc));
}

// ------------------------------ launcher -----------------------------------
extern "C" void kernel_launch(void* const* d_in, const int* in_sizes, int n_in,
                              void* d_out, int out_size)
{
    const float* features = (const float*)d_in[0];
    const float* coord_w  = (const float*)d_in[1];
    const float* coord_b  = (const float*)d_in[2];
    const float* bn1g = (const float*)d_in[3];
    const float* bn1b = (const float*)d_in[4];
    const float* bn1m = (const float*)d_in[5];
    const float* bn1v = (const float*)d_in[6];
    const float* off_w = (const float*)d_in[7];
    const float* off_b = (const float*)d_in[8];
    const float* dc_w  = (const float*)d_in[9];
    const float* bn2g = (const float*)d_in[10];
    const float* bn2b = (const float*)d_in[11];
    const float* bn2m = (const float*)d_in[12];
    const float* bn2v = (const float*)d_in[13];
    const float* r1_w = (const float*)d_in[14];
    const float* bn3g = (const float*)d_in[15];
    const float* bn3b = (const float*)d_in[16];
    const float* bn3m = (const float*)d_in[17];
    const float* bn3v = (const float*)d_in[18];
    const float* r2_w = (const float*)d_in[19];
    const float* bn4g = (const float*)d_in[20];
    const float* bn4b = (const float*)d_in[21];
    const float* bn4m = (const float*)d_in[22];
    const float* bn4v = (const float*)d_in[23];
    const float* out_w = (const float*)d_in[24];
    const float* out_b = (const float*)d_in[25];

    float *p_buf0, *p_buf1, *p_off, *p_samp, *p_w1t, *p_cb, *p_wofft,
          *p_wdct, *p_wr1t, *p_wr2t, *p_bnsc, *p_bnsh;
    cudaGetSymbolAddress((void**)&p_buf0, g_buf0);
    cudaGetSymbolAddress((void**)&p_buf1, g_buf1);
    cudaGetSymbolAddress((void**)&p_off,  g_offb);
    cudaGetSymbolAddress((void**)&p_samp, g_samp);
    cudaGetSymbolAddress((void**)&p_w1t,  g_w1t);
    cudaGetSymbolAddress((void**)&p_cb,   g_cb);
    cudaGetSymbolAddress((void**)&p_wofft, g_wofft);
    cudaGetSymbolAddress((void**)&p_wdct, g_wdct);
    cudaGetSymbolAddress((void**)&p_wr1t, g_wr1t);
    cudaGetSymbolAddress((void**)&p_wr2t, g_wr2t);
    cudaGetSymbolAddress((void**)&p_bnsc, g_bnsc);
    cudaGetSymbolAddress((void**)&p_bnsh, g_bnsh);

    // 1. prep: repack + tf32-truncate weights, coord bias map, folded BN
    const int prep_total = 2304 * 64 + 96 * 96 * 64 + 4 * 576 * 64 + 512;
    prep_kernel<<<(prep_total + 255) / 256, 256>>>(
        coord_w, coord_b, off_w, dc_w, r1_w, r2_w,
        bn1g, bn1b, bn1m, bn1v, bn2g, bn2b, bn2m, bn2v,
        bn3g, bn3b, bn3m, bn3v, bn4g, bn4b, bn4m, bn4v);

    dim3 grid(3, 24, 8);   // 32 x-cols, 4 rows per block -> 128 positions

    // 2. coord conv (256->64) + coord bias + BN1 + ReLU -> buf0
    conv_mma<256, 9, 0><<<grid, 256>>>(
        features, p_w1t, p_cb, nullptr, p_bnsc + 0, p_bnsh + 0, p_buf0);

    // 3. offset conv (64->18, padded 64) + bias -> g_offb
    conv_mma<64, 9, 1><<<grid, 256>>>(
        p_buf0, p_wofft, nullptr, off_b, nullptr, nullptr, p_off);

    // 4. deform bilinear sampling -> g_samp
    sample_kernel<<<(sh::kPos * 16 + 255) / 256, 256>>>(p_buf0, p_off, p_samp);

    // 5. deform einsum (K=576) + BN2 + ReLU -> buf1
    conv_mma<576, 1, 2><<<grid, 256>>>(
        p_samp, p_wdct, nullptr, nullptr, p_bnsc + 64, p_bnsh + 64, p_buf1);

    // 6. r1 conv + BN3 + ReLU -> buf0
    conv_mma<64, 9, 2><<<grid, 256>>>(
        p_buf1, p_wr1t, nullptr, nullptr, p_bnsc + 128, p_bnsh + 128, p_buf0);

    // 7. r2 conv + BN4 + ReLU -> buf1
    conv_mma<64, 9, 2><<<grid, 256>>>(
        p_buf0, p_wr2t, nullptr, nullptr, p_bnsc + 192, p_bnsh + 192, p_buf1);

    // 8. 1x1 conv + sigmoid -> d_out
    final_kernel<<<(sh::kPos + 255) / 256, 256>>>(
        p_buf1, out_w, out_b, (float*)d_out);
}

// round 4
// speedup vs baseline: 2.9582x; 1.1156x over previous
#include <cuda_runtime.h>
#include <math.h>
#include <stdint.h>

// ---------------------------------------------------------------------------
// SpatialHead on sm_103a — TF32 mma + cp.async double-buffered implicit GEMM.
// coordconv(256+2->64)+BN+ReLU -> offsetconv(64->18) -> deformconv(64->64)
// +BN+ReLU -> 2x [conv3x3(64->64)+BN+ReLU] -> 1x1 conv -> sigmoid
// B=8, H=W=96. Activations NHWC fp32 (truncated to tf32 by mma HW);
// weights pre-rounded to tf32 in prep.
// ---------------------------------------------------------------------------

namespace sh {
constexpr int kB = 8, kH = 96, kW = 96;
constexpr int kPos = kB * kH * kW;          // 73728
constexpr float kEps = 1e-5f;
}

// ------------------------- scratch (__device__ globals) --------------------
__device__ __align__(16) float g_buf0[sh::kPos * 64];
__device__ __align__(16) float g_buf1[sh::kPos * 64];
__device__ __align__(16) float g_offb[sh::kPos * 18];
__device__ __align__(16) float g_samp[(size_t)sh::kPos * 576];
__device__ __align__(16) float g_w1t[2304 * 64];               // coord conv [k][o] tf32
__device__ __align__(16) float g_cb[sh::kH * sh::kW * 64];     // coord bias map fp32
__device__ __align__(16) float g_wofft[576 * 64];              // offset conv padded, tf32
__device__ __align__(16) float g_wdct[576 * 64];
__device__ __align__(16) float g_wr1t[576 * 64];
__device__ __align__(16) float g_wr2t[576 * 64];
__device__ float g_bnsc[4 * 64];
__device__ float g_bnsh[4 * 64];

// ------------------------------ helpers ------------------------------------
__device__ __forceinline__ float f2tf32(float x) {
    uint32_t r;
    asm("cvt.rna.tf32.f32 %0, %1;" : "=r"(r) : "f"(x));
    return __uint_as_float(r);
}
__device__ __forceinline__ unsigned smem_u32(const void* p) {
    unsigned a;
    asm("{ .reg .u64 t; cvta.to.shared.u64 t, %1; cvt.u32.u64 %0, t; }"
        : "=r"(a) : "l"(p));
    return a;
}
__device__ __forceinline__ void cp_async16(unsigned dst, const void* src, bool ok) {
    int sz = ok ? 16 : 0;
    asm volatile("cp.async.cg.shared.global [%0], [%1], 16, %2;\n"
                 :: "r"(dst), "l"(src), "r"(sz));
}
__device__ __forceinline__ void cp_commit() {
    asm volatile("cp.async.commit_group;\n");
}
template <int N>
__device__ __forceinline__ void cp_wait() {
    asm volatile("cp.async.wait_group %0;\n" :: "n"(N));
}
__device__ __forceinline__ void mma_tf32(float c[4], const uint32_t a[4],
                                         uint32_t b0, uint32_t b1) {
    asm volatile(
        "mma.sync.aligned.m16n8k8.row.col.f32.tf32.tf32.f32 "
        "{%0,%1,%2,%3}, {%4,%5,%6,%7}, {%8,%9}, {%0,%1,%2,%3};\n"
        : "+f"(c[0]), "+f"(c[1]), "+f"(c[2]), "+f"(c[3])
        : "r"(a[0]), "r"(a[1]), "r"(a[2]), "r"(a[3]), "r"(b0), "r"(b1));
}

// ------------------------------ prep kernel --------------------------------
__global__ void prep_kernel(
    const float* __restrict__ coord_w, const float* __restrict__ coord_b,
    const float* __restrict__ off_w, const float* __restrict__ dc_w,
    const float* __restrict__ r1_w, const float* __restrict__ r2_w,
    const float* __restrict__ bn1g, const float* __restrict__ bn1b,
    const float* __restrict__ bn1m, const float* __restrict__ bn1v,
    const float* __restrict__ bn2g, const float* __restrict__ bn2b,
    const float* __restrict__ bn2m, const float* __restrict__ bn2v,
    const float* __restrict__ bn3g, const float* __restrict__ bn3b,
    const float* __restrict__ bn3m, const float* __restrict__ bn3v,
    const float* __restrict__ bn4g, const float* __restrict__ bn4b,
    const float* __restrict__ bn4m, const float* __restrict__ bn4v)
{
    int idx = blockIdx.x * blockDim.x + threadIdx.x;
    const int N1 = 2304 * 64;
    const int N2 = sh::kH * sh::kW * 64;
    const int N3 = 576 * 64;

    if (idx < N1) {
        int o = idx & 63, k = idx >> 6;
        int t = k >> 8, c = k & 255;
        g_w1t[idx] = f2tf32(coord_w[(o * 258 + c) * 9 + t]);
        return;
    }
    idx -= N1;
    if (idx < N2) {
        int o = idx & 63, p = idx >> 6;
        int y = p / 96, x = p % 96;
        float acc = coord_b[o];
        #pragma unroll
        for (int t = 0; t < 9; t++) {
            int yy = y + t / 3 - 1, xx = x + t % 3 - 1;
            if ((unsigned)yy < 96u && (unsigned)xx < 96u) {
                float xv = fmaf((float)xx, 2.0f / 95.0f, -1.0f);
                float yv = fmaf((float)yy, 2.0f / 95.0f, -1.0f);
                acc = fmaf(coord_w[(o * 258 + 256) * 9 + t], xv, acc);
                acc = fmaf(coord_w[(o * 258 + 257) * 9 + t], yv, acc);
            }
        }
        g_cb[p * 64 + o] = acc;
        return;
    }
    idx -= N2;
    if (idx < N3) {
        int o = idx & 63, k = idx >> 6;
        int t = k >> 6, c = k & 63;
        g_wofft[idx] = (o < 18) ? f2tf32(off_w[(o * 64 + c) * 9 + t]) : 0.0f;
        return;
    }
    idx -= N3;
    if (idx < N3) {
        int o = idx & 63, k = idx >> 6;
        int t = k >> 6, c = k & 63;
        g_wdct[idx] = f2tf32(dc_w[(o * 64 + c) * 9 + t]);
        return;
    }
    idx -= N3;
    if (idx < N3) {
        int o = idx & 63, k = idx >> 6;
        int t = k >> 6, c = k & 63;
        g_wr1t[idx] = f2tf32(r1_w[(o * 64 + c) * 9 + t]);
        return;
    }
    idx -= N3;
    if (idx < N3) {
        int o = idx & 63, k = idx >> 6;
        int t = k >> 6, c = k & 63;
        g_wr2t[idx] = f2tf32(r2_w[(o * 64 + c) * 9 + t]);
        return;
    }
    idx -= N3;
    if (idx < 512) {
        int which = idx >> 7, r = idx & 127, o = r & 63;
        const float* gs; const float* bs; const float* ms; const float* vs;
        if (which == 0)      { gs = bn1g; bs = bn1b; ms = bn1m; vs = bn1v; }
        else if (which == 1) { gs = bn2g; bs = bn2b; ms = bn2m; vs = bn2v; }
        else if (which == 2) { gs = bn3g; bs = bn3b; ms = bn3m; vs = bn3v; }
        else                 { gs = bn4g; bs = bn4b; ms = bn4m; vs = bn4v; }
        float sc = gs[o] * rsqrtf(vs[o] + sh::kEps);
        if (r < 64) g_bnsc[which * 64 + o] = sc;
        else        g_bnsh[which * 64 + o] = bs[o] - ms[o] * sc;
    }
}

// --------------------------- conv GEMM (mma + cp.async) --------------------
// Block: 256 positions (8 rows x 32 cols) x 64 cout, 256 threads (8 warps).
// Warp grid 4(M) x 2(N): warp tile m64 x n32 = 4x4 mma.m16n8k8 tiles.
// Double-buffered cp.async: A [pos][c] pitch 36, B [k][n] pitch 72
// (both conflict-free for fragment LDS). Activations raw fp32 -> HW tf32
// truncation; weights pre-rounded.
// MODE 0: + per-position bias + BN + ReLU   (coord conv)
// MODE 1: + channel bias, store 18 channels (offset conv)
// MODE 2: + BN + ReLU                       (deform / r1 / r2)
constexpr int APITCH = 36;
constexpr int BPITCH = 72;
constexpr int ABUF = 256 * APITCH;          // floats per A stage
constexpr int BBUF = 32 * BPITCH;           // floats per B stage
constexpr int SMEM_FLOATS = 2 * ABUF + 2 * BBUF;
constexpr int SMEM_BYTES = SMEM_FLOATS * 4; // 92160

template <int CIN, int TAPS, int MODE>
__global__ void __launch_bounds__(256, 2)
conv_mma(const float* __restrict__ in, const float* __restrict__ wT,
         const float* __restrict__ posbias, const float* __restrict__ chbias,
         const float* __restrict__ bnsc, const float* __restrict__ bnsh,
         float* __restrict__ out)
{
    constexpr int CPT = CIN / 32;
    constexpr int KCH = TAPS * CPT;
    extern __shared__ float smem[];
    const unsigned aBase = smem_u32(smem);
    const unsigned bBase = aBase + 2 * ABUF * 4;

    const int tid = threadIdx.x;
    const int wid = tid >> 5;
    const int lane = tid & 31;
    const int warpM = wid & 3;           // m64 each
    const int warpN = wid >> 2;          // n32 each
    const int g = lane >> 2;             // 0..7
    const int tg = lane & 3;             // 0..3

    const int x0 = blockIdx.x * 32;
    const int ybase = blockIdx.y * 8;
    const int b = blockIdx.z;

    // this thread's fill position (one row of 32 channels per chunk)
    const int fp = tid;                          // 0..255
    const int fpy = fp >> 5, fpx = fp & 31;

    float c[4][4][4];
    #pragma unroll
    for (int mt = 0; mt < 4; mt++)
        #pragma unroll
        for (int nt = 0; nt < 4; nt++)
            #pragma unroll
            for (int r = 0; r < 4; r++) c[mt][nt][r] = 0.0f;

    auto prefetch = [&](int ch, int buf) {
        const int t = (TAPS == 1) ? 0 : (ch / CPT);
        const int c0 = (ch % CPT) * 32;
        const int dy = (TAPS == 1) ? 0 : (t / 3 - 1);
        const int dx = (TAPS == 1) ? 0 : (t % 3 - 1);
        // A: 256 pos x 32 ch
        const int yy = ybase + fpy + dy;
        const int xx = x0 + fpx + dx;
        const bool ok = (TAPS == 1) || ((unsigned)yy < 96u && (unsigned)xx < 96u);
        const float* src = ok
            ? in + (size_t)((b * 96 + yy) * 96 + xx) * CIN + c0
            : in;
        unsigned dstA = aBase + (unsigned)(buf * ABUF + fp * APITCH) * 4u;
        #pragma unroll
        for (int s = 0; s < 8; s++)
            cp_async16(dstA + s * 16, src + s * 4, ok);
        // B: 32 k x 64 n
        const int r = tid >> 3;
        const int cp = tid & 7;
        const float* ws = wT + (size_t)(ch * 32 + r) * 64 + cp * 8;
        unsigned dstB = bBase + (unsigned)(buf * BBUF + r * BPITCH) * 4u + cp * 32u;
        cp_async16(dstB, ws, true);
        cp_async16(dstB + 16, ws + 4, true);
    };

    prefetch(0, 0);
    cp_commit();

    for (int ch = 0; ch < KCH; ch++) {
        if (ch + 1 < KCH) prefetch(ch + 1, (ch + 1) & 1);
        cp_commit();
        cp_wait<1>();
        __syncthreads();

        const float* A = smem + (ch & 1) * ABUF;
        const float* Bt = smem + 2 * ABUF + (ch & 1) * BBUF;

        #pragma unroll
        for (int ks = 0; ks < 4; ks++) {
            const int k0 = ks * 8;
            uint32_t a[4][4];
            #pragma unroll
            for (int mt = 0; mt < 4; mt++) {
                const int m0 = warpM * 64 + mt * 16;
                a[mt][0] = __float_as_uint(A[(m0 + g) * APITCH + k0 + tg]);
                a[mt][1] = __float_as_uint(A[(m0 + g + 8) * APITCH + k0 + tg]);
                a[mt][2] = __float_as_uint(A[(m0 + g) * APITCH + k0 + tg + 4]);
                a[mt][3] = __float_as_uint(A[(m0 + g + 8) * APITCH + k0 + tg + 4]);
            }
            #pragma unroll
            for (int nt = 0; nt < 4; nt++) {
                const int n0 = warpN * 32 + nt * 8;
                uint32_t b0 = __float_as_uint(Bt[(k0 + tg) * BPITCH + n0 + g]);
                uint32_t b1 = __float_as_uint(Bt[(k0 + tg + 4) * BPITCH + n0 + g]);
                #pragma unroll
                for (int mt = 0; mt < 4; mt++)
                    mma_tf32(c[mt][nt], a[mt], b0, b1);
            }
        }
        __syncthreads();
    }

    // ------------------------------- epilogue -------------------------------
    #pragma unroll
    for (int mt = 0; mt < 4; mt++) {
        #pragma unroll
        for (int rr = 0; rr < 2; rr++) {
            const int m = warpM * 64 + mt * 16 + rr * 8 + g;
            const int py = ybase + (m >> 5);
            const int px = x0 + (m & 31);
            const size_t pos = ((size_t)b * 96 + py) * 96 + px;
            #pragma unroll
            for (int nt = 0; nt < 4; nt++) {
                const int o = warpN * 32 + nt * 8 + tg * 2;
                float v0 = c[mt][nt][rr * 2 + 0];
                float v1 = c[mt][nt][rr * 2 + 1];
                if constexpr (MODE == 0) {
                    const float2 pb = *(const float2*)&posbias[(size_t)(py * 96 + px) * 64 + o];
                    v0 += pb.x; v1 += pb.y;
                    const float2 sc = *(const float2*)&bnsc[o];
                    const float2 shb = *(const float2*)&bnsh[o];
                    v0 = fmaxf(fmaf(v0, sc.x, shb.x), 0.0f);
                    v1 = fmaxf(fmaf(v1, sc.y, shb.y), 0.0f);
                    *(float2*)&out[pos * 64 + o] = make_float2(v0, v1);
                } else if constexpr (MODE == 1) {
                    if (o < 18)     out[pos * 18 + o]     = v0 + chbias[o];
                    if (o + 1 < 18) out[pos * 18 + o + 1] = v1 + chbias[o + 1];
                } else {
                    const float2 sc = *(const float2*)&bnsc[o];
                    const float2 shb = *(const float2*)&bnsh[o];
                    v0 = fmaxf(fmaf(v0, sc.x, shb.x), 0.0f);
                    v1 = fmaxf(fmaf(v1, sc.y, shb.y), 0.0f);
                    *(float2*)&out[pos * 64 + o] = make_float2(v0, v1);
                }
            }
        }
    }
}

// --------------------------- deform sampling -------------------------------
__device__ __forceinline__ void corner_acc(const float4* __restrict__ base,
                                           int yy, int xx, int cq, float w,
                                           float4& acc)
{
    if ((unsigned)yy < 96u && (unsigned)xx < 96u) {
        float4 vv = base[(yy * 96 + xx) * 16 + cq];
        acc.x = fmaf(w, vv.x, acc.x);
        acc.y = fmaf(w, vv.y, acc.y);
        acc.z = fmaf(w, vv.z, acc.z);
        acc.w = fmaf(w, vv.w, acc.w);
    }
}

__global__ void sample_kernel(const float* __restrict__ x1,
                              const float* __restrict__ offs,
                              float* __restrict__ samp)
{
    int gid = blockIdx.x * blockDim.x + threadIdx.x;   // kPos * 16
    if (gid >= sh::kPos * 16) return;
    const int cq = gid & 15;
    const int pos = gid >> 4;
    const int b = pos / (sh::kH * sh::kW);
    const int rem = pos % (sh::kH * sh::kW);
    const int y = rem / sh::kW, x = rem % sh::kW;

    const float* op = offs + (size_t)pos * 18;
    const float4* base = (const float4*)x1 + (size_t)(b * sh::kH * sh::kW) * 16;
    float4* outp = (float4*)(samp + (size_t)pos * 576);

    #pragma unroll
    for (int t = 0; t < 9; t++) {
        float oy = op[2 * t];
        float ox = op[2 * t + 1];
        float py = (float)(y + t / 3 - 1) + oy;
        float px = (float)(x + t % 3 - 1) + ox;
        float y0f = floorf(py), x0f = floorf(px);
        float fy = py - y0f, fx = px - x0f;
        int y0 = (int)y0f, xx0 = (int)x0f;
        float w00 = (1.0f - fy) * (1.0f - fx);
        float w01 = (1.0f - fy) * fx;
        float w10 = fy * (1.0f - fx);
        float w11 = fy * fx;
        float4 acc = make_float4(0.f, 0.f, 0.f, 0.f);
        corner_acc(base, y0,     xx0,     cq, w00, acc);
        corner_acc(base, y0,     xx0 + 1, cq, w01, acc);
        corner_acc(base, y0 + 1, xx0,     cq, w10, acc);
        corner_acc(base, y0 + 1, xx0 + 1, cq, w11, acc);
        outp[t * 16 + cq] = acc;
    }
}

// ------------------------------ final 1x1 ----------------------------------
__global__ void final_kernel(const float* __restrict__ x4,
                             const float* __restrict__ ow,
                             const float* __restrict__ ob,
                             float* __restrict__ out)
{
    int pos = blockIdx.x * blockDim.x + threadIdx.x;
    if (pos >= sh::kPos) return;
    const float4* xr = (const float4*)(x4 + (size_t)pos * 64);
    const float4* wr = (const float4*)ow;
    float acc = ob[0];
    #pragma unroll
    for (int q = 0; q < 16; q++) {
        float4 a = xr[q], w = wr[q];
        acc = fmaf(a.x, w.x, acc);
        acc = fmaf(a.y, w.y, acc);
        acc = fmaf(a.z, w.z, acc);
        acc = fmaf(a.w, w.w, acc);
    }
    out[pos] = 1.0f / (1.0f + expf(-acc));
}

// ------------------------------ launcher -----------------------------------
extern "C" void kernel_launch(void* const* d_in, const int* in_sizes, int n_in,
                              void* d_out, int out_size)
{
    const float* features = (const float*)d_in[0];
    const float* coord_w  = (const float*)d_in[1];
    const float* coord_b  = (const float*)d_in[2];
    const float* bn1g = (const float*)d_in[3];
    const float* bn1b = (const float*)d_in[4];
    const float* bn1m = (const float*)d_in[5];
    const float* bn1v = (const float*)d_in[6];
    const float* off_w = (const float*)d_in[7];
    const float* off_b = (const float*)d_in[8];
    const float* dc_w  = (const float*)d_in[9];
    const float* bn2g = (const float*)d_in[10];
    const float* bn2b = (const float*)d_in[11];
    const float* bn2m = (const float*)d_in[12];
    const float* bn2v = (const float*)d_in[13];
    const float* r1_w = (const float*)d_in[14];
    const float* bn3g = (const float*)d_in[15];
    const float* bn3b = (const float*)d_in[16];
    const float* bn3m = (const float*)d_in[17];
    const float* bn3v = (const float*)d_in[18];
    const float* r2_w = (const float*)d_in[19];
    const float* bn4g = (const float*)d_in[20];
    const float* bn4b = (const float*)d_in[21];
    const float* bn4m = (const float*)d_in[22];
    const float* bn4v = (const float*)d_in[23];
    const float* out_w = (const float*)d_in[24];
    const float* out_b = (const float*)d_in[25];

    float *p_buf0, *p_buf1, *p_off, *p_samp, *p_w1t, *p_cb, *p_wofft,
          *p_wdct, *p_wr1t, *p_wr2t, *p_bnsc, *p_bnsh;
    cudaGetSymbolAddress((void**)&p_buf0, g_buf0);
    cudaGetSymbolAddress((void**)&p_buf1, g_buf1);
    cudaGetSymbolAddress((void**)&p_off,  g_offb);
    cudaGetSymbolAddress((void**)&p_samp, g_samp);
    cudaGetSymbolAddress((void**)&p_w1t,  g_w1t);
    cudaGetSymbolAddress((void**)&p_cb,   g_cb);
    cudaGetSymbolAddress((void**)&p_wofft, g_wofft);
    cudaGetSymbolAddress((void**)&p_wdct, g_wdct);
    cudaGetSymbolAddress((void**)&p_wr1t, g_wr1t);
    cudaGetSymbolAddress((void**)&p_wr2t, g_wr2t);
    cudaGetSymbolAddress((void**)&p_bnsc, g_bnsc);
    cudaGetSymbolAddress((void**)&p_bnsh, g_bnsh);

    // allow >48KB dynamic smem (host-side attribute, idempotent)
    cudaFuncSetAttribute(conv_mma<256, 9, 0>,
                         cudaFuncAttributeMaxDynamicSharedMemorySize, SMEM_BYTES);
    cudaFuncSetAttribute(conv_mma<64, 9, 1>,
                         cudaFuncAttributeMaxDynamicSharedMemorySize, SMEM_BYTES);
    cudaFuncSetAttribute(conv_mma<576, 1, 2>,
                         cudaFuncAttributeMaxDynamicSharedMemorySize, SMEM_BYTES);
    cudaFuncSetAttribute(conv_mma<64, 9, 2>,
                         cudaFuncAttributeMaxDynamicSharedMemorySize, SMEM_BYTES);

    // 1. prep
    const int prep_total = 2304 * 64 + 96 * 96 * 64 + 4 * 576 * 64 + 512;
    prep_kernel<<<(prep_total + 255) / 256, 256>>>(
        coord_w, coord_b, off_w, dc_w, r1_w, r2_w,
        bn1g, bn1b, bn1m, bn1v, bn2g, bn2b, bn2m, bn2v,
        bn3g, bn3b, bn3m, bn3v, bn4g, bn4b, bn4m, bn4v);

    dim3 grid(3, 12, 8);   // 32 x-cols, 8 rows per block -> 256 positions

    // 2. coord conv (256->64) + coord bias + BN1 + ReLU -> buf0
    conv_mma<256, 9, 0><<<grid, 256, SMEM_BYTES>>>(
        features, p_w1t, p_cb, nullptr, p_bnsc + 0, p_bnsh + 0, p_buf0);

    // 3. offset conv (64->18, padded 64) + bias -> g_offb
    conv_mma<64, 9, 1><<<grid, 256, SMEM_BYTES>>>(
        p_buf0, p_wofft, nullptr, off_b, nullptr, nullptr, p_off);

    // 4. deform bilinear sampling -> g_samp
    sample_kernel<<<(sh::kPos * 16 + 255) / 256, 256>>>(p_buf0, p_off, p_samp);

    // 5. deform einsum (K=576) + BN2 + ReLU -> buf1
    conv_mma<576, 1, 2><<<grid, 256, SMEM_BYTES>>>(
        p_samp, p_wdct, nullptr, nullptr, p_bnsc + 64, p_bnsh + 64, p_buf1);

    // 6. r1 conv + BN3 + ReLU -> buf0
    conv_mma<64, 9, 2><<<grid, 256, SMEM_BYTES>>>(
        p_buf1, p_wr1t, nullptr, nullptr, p_bnsc + 128, p_bnsh + 128, p_buf0);

    // 7. r2 conv + BN4 + ReLU -> buf1
    conv_mma<64, 9, 2><<<grid, 256, SMEM_BYTES>>>(
        p_buf0, p_wr2t, nullptr, nullptr, p_bnsc + 192, p_bnsh + 192, p_buf1);

    // 8. 1x1 conv + sigmoid -> d_out
    final_kernel<<<(sh::kPos + 255) / 256, 256>>>(
        p_buf1, out_w, out_b, (float*)d_out);
}

// round 5
// speedup vs baseline: 3.1316x; 1.0586x over previous
#include <cuda_runtime.h>
#include <math.h>
#include <stdint.h>

// ---------------------------------------------------------------------------
// SpatialHead on sm_103a — TF32 mma + 4-stage cp.async implicit GEMM.
// coordconv(256+2->64)+BN+ReLU -> offsetconv(64->18) -> deformconv(64->64)
// +BN+ReLU -> 2x [conv3x3(64->64)+BN+ReLU] -> 1x1 conv -> sigmoid
// B=8, H=W=96. Activations NHWC fp32 (HW-truncated to tf32 in mma);
// weights pre-rounded to tf32 in prep.
// ---------------------------------------------------------------------------

namespace sh {
constexpr int kB = 8, kH = 96, kW = 96;
constexpr int kPos = kB * kH * kW;          // 73728
constexpr float kEps = 1e-5f;
}

// ------------------------- scratch (__device__ globals) --------------------
__device__ __align__(16) float g_buf0[sh::kPos * 64];
__device__ __align__(16) float g_buf1[sh::kPos * 64];
__device__ __align__(16) float g_offb[sh::kPos * 18];
__device__ __align__(16) float g_samp[(size_t)sh::kPos * 576];
__device__ __align__(16) float g_w1t[2304 * 64];               // coord conv [k][o] tf32
__device__ __align__(16) float g_cb[sh::kH * sh::kW * 64];     // coord bias map fp32
__device__ __align__(16) float g_wofft[576 * 64];              // offset conv padded, tf32
__device__ __align__(16) float g_wdct[576 * 64];
__device__ __align__(16) float g_wr1t[576 * 64];
__device__ __align__(16) float g_wr2t[576 * 64];
__device__ float g_bnsc[4 * 64];
__device__ float g_bnsh[4 * 64];

// ------------------------------ helpers ------------------------------------
__device__ __forceinline__ float f2tf32(float x) {
    uint32_t r;
    asm("cvt.rna.tf32.f32 %0, %1;" : "=r"(r) : "f"(x));
    return __uint_as_float(r);
}
__device__ __forceinline__ unsigned smem_u32(const void* p) {
    unsigned a;
    asm("{ .reg .u64 t; cvta.to.shared.u64 t, %1; cvt.u32.u64 %0, t; }"
        : "=r"(a) : "l"(p));
    return a;
}
__device__ __forceinline__ void cp_async16(unsigned dst, const void* src, bool ok) {
    int sz = ok ? 16 : 0;
    asm volatile("cp.async.cg.shared.global [%0], [%1], 16, %2;\n"
                 :: "r"(dst), "l"(src), "r"(sz));
}
__device__ __forceinline__ void cp_commit() {
    asm volatile("cp.async.commit_group;\n");
}
template <int N>
__device__ __forceinline__ void cp_wait() {
    asm volatile("cp.async.wait_group %0;\n" :: "n"(N));
}
__device__ __forceinline__ void mma_tf32(float c[4], const uint32_t a[4],
                                         uint32_t b0, uint32_t b1) {
    asm volatile(
        "mma.sync.aligned.m16n8k8.row.col.f32.tf32.tf32.f32 "
        "{%0,%1,%2,%3}, {%4,%5,%6,%7}, {%8,%9}, {%0,%1,%2,%3};\n"
        : "+f"(c[0]), "+f"(c[1]), "+f"(c[2]), "+f"(c[3])
        : "r"(a[0]), "r"(a[1]), "r"(a[2]), "r"(a[3]), "r"(b0), "r"(b1));
}

// ------------------------------ prep kernel --------------------------------
__global__ void prep_kernel(
    const float* __restrict__ coord_w, const float* __restrict__ coord_b,
    const float* __restrict__ off_w, const float* __restrict__ dc_w,
    const float* __restrict__ r1_w, const float* __restrict__ r2_w,
    const float* __restrict__ bn1g, const float* __restrict__ bn1b,
    const float* __restrict__ bn1m, const float* __restrict__ bn1v,
    const float* __restrict__ bn2g, const float* __restrict__ bn2b,
    const float* __restrict__ bn2m, const float* __restrict__ bn2v,
    const float* __restrict__ bn3g, const float* __restrict__ bn3b,
    const float* __restrict__ bn3m, const float* __restrict__ bn3v,
    const float* __restrict__ bn4g, const float* __restrict__ bn4b,
    const float* __restrict__ bn4m, const float* __restrict__ bn4v)
{
    int idx = blockIdx.x * blockDim.x + threadIdx.x;
    const int N1 = 2304 * 64;
    const int N2 = sh::kH * sh::kW * 64;
    const int N3 = 576 * 64;

    if (idx < N1) {
        int o = idx & 63, k = idx >> 6;
        int t = k >> 8, c = k & 255;
        g_w1t[idx] = f2tf32(coord_w[(o * 258 + c) * 9 + t]);
        return;
    }
    idx -= N1;
    if (idx < N2) {
        int o = idx & 63, p = idx >> 6;
        int y = p / 96, x = p % 96;
        float acc = coord_b[o];
        #pragma unroll
        for (int t = 0; t < 9; t++) {
            int yy = y + t / 3 - 1, xx = x + t % 3 - 1;
            if ((unsigned)yy < 96u && (unsigned)xx < 96u) {
                float xv = fmaf((float)xx, 2.0f / 95.0f, -1.0f);
                float yv = fmaf((float)yy, 2.0f / 95.0f, -1.0f);
                acc = fmaf(coord_w[(o * 258 + 256) * 9 + t], xv, acc);
                acc = fmaf(coord_w[(o * 258 + 257) * 9 + t], yv, acc);
            }
        }
        g_cb[p * 64 + o] = acc;
        return;
    }
    idx -= N2;
    if (idx < N3) {
        int o = idx & 63, k = idx >> 6;
        int t = k >> 6, c = k & 63;
        g_wofft[idx] = (o < 18) ? f2tf32(off_w[(o * 64 + c) * 9 + t]) : 0.0f;
        return;
    }
    idx -= N3;
    if (idx < N3) {
        int o = idx & 63, k = idx >> 6;
        int t = k >> 6, c = k & 63;
        g_wdct[idx] = f2tf32(dc_w[(o * 64 + c) * 9 + t]);
        return;
    }
    idx -= N3;
    if (idx < N3) {
        int o = idx & 63, k = idx >> 6;
        int t = k >> 6, c = k & 63;
        g_wr1t[idx] = f2tf32(r1_w[(o * 64 + c) * 9 + t]);
        return;
    }
    idx -= N3;
    if (idx < N3) {
        int o = idx & 63, k = idx >> 6;
        int t = k >> 6, c = k & 63;
        g_wr2t[idx] = f2tf32(r2_w[(o * 64 + c) * 9 + t]);
        return;
    }
    idx -= N3;
    if (idx < 512) {
        int which = idx >> 7, r = idx & 127, o = r & 63;
        const float* gs; const float* bs; const float* ms; const float* vs;
        if (which == 0)      { gs = bn1g; bs = bn1b; ms = bn1m; vs = bn1v; }
        else if (which == 1) { gs = bn2g; bs = bn2b; ms = bn2m; vs = bn2v; }
        else if (which == 2) { gs = bn3g; bs = bn3b; ms = bn3m; vs = bn3v; }
        else                 { gs = bn4g; bs = bn4b; ms = bn4m; vs = bn4v; }
        float sc = gs[o] * rsqrtf(vs[o] + sh::kEps);
        if (r < 64) g_bnsc[which * 64 + o] = sc;
        else        g_bnsh[which * 64 + o] = bs[o] - ms[o] * sc;
    }
}

// --------------------------- conv GEMM (mma + 4-stage cp.async) ------------
// Block: 128 positions (4 rows x 32 cols) x 64 cout, 256 threads (8 warps).
// Warp grid 4(M) x 2(N): warp tile m32 x n32 = 2x4 mma.m16n8k8 tiles.
// 4-stage cp.async pipeline, one __syncthreads per chunk.
// A [pos][c] pitch 36, B [k][n] pitch 72 (fragment LDS conflict-free).
// MODE 0: + per-position bias + BN + ReLU   (coord conv)
// MODE 1: + channel bias, store 18 channels (offset conv)
// MODE 2: + BN + ReLU                       (deform / r1 / r2)
constexpr int STAGES = 4;
constexpr int APITCH = 36;
constexpr int BPITCH = 72;
constexpr int ABUF = 128 * APITCH;          // floats per A stage (4608)
constexpr int BBUF = 32 * BPITCH;           // floats per B stage (2304)
constexpr int SMEM_BYTES = STAGES * (ABUF + BBUF) * 4;   // 110592

template <int CIN, int TAPS, int MODE>
__global__ void __launch_bounds__(256, 2)
conv_mma(const float* __restrict__ in, const float* __restrict__ wT,
         const float* __restrict__ posbias, const float* __restrict__ chbias,
         const float* __restrict__ bnsc, const float* __restrict__ bnsh,
         float* __restrict__ out)
{
    constexpr int CPT = CIN / 32;
    constexpr int KCH = TAPS * CPT;
    extern __shared__ float smem[];
    const unsigned aBase = smem_u32(smem);
    const unsigned bBase = aBase + STAGES * ABUF * 4;

    const int tid = threadIdx.x;
    const int wid = tid >> 5;
    const int lane = tid & 31;
    const int warpM = wid & 3;           // m32 each
    const int warpN = wid >> 2;          // n32 each
    const int g = lane >> 2;             // 0..7
    const int tg = lane & 3;             // 0..3

    const int x0 = blockIdx.x * 32;
    const int ybase = blockIdx.y * 4;
    const int b = blockIdx.z;

    // fill mapping: each thread covers half of one position's 32 channels
    const int fp = tid >> 1;                    // 0..127
    const int fhalf = (tid & 1) * 16;           // channel half
    const int fpy = fp >> 5, fpx = fp & 31;

    float c[2][4][4];
    #pragma unroll
    for (int mt = 0; mt < 2; mt++)
        #pragma unroll
        for (int nt = 0; nt < 4; nt++)
            #pragma unroll
            for (int r = 0; r < 4; r++) c[mt][nt][r] = 0.0f;

    auto prefetch = [&](int ch) {
        const int s = ch % STAGES;
        const int t = (TAPS == 1) ? 0 : (ch / CPT);
        const int c0 = (ch % CPT) * 32;
        const int dy = (TAPS == 1) ? 0 : (t / 3 - 1);
        const int dx = (TAPS == 1) ? 0 : (t % 3 - 1);
        // A: 128 pos x 32 ch -> 4 x cp.async16 per thread
        const int yy = ybase + fpy + dy;
        const int xx = x0 + fpx + dx;
        const bool ok = (TAPS == 1) || ((unsigned)yy < 96u && (unsigned)xx < 96u);
        const float* src = ok
            ? in + (size_t)((b * 96 + yy) * 96 + xx) * CIN + c0 + fhalf
            : in;
        unsigned dstA = aBase + (unsigned)(s * ABUF + fp * APITCH + fhalf) * 4u;
        #pragma unroll
        for (int q = 0; q < 4; q++)
            cp_async16(dstA + q * 16, src + q * 4, ok);
        // B: 32 k x 64 n -> 2 x cp.async16 per thread
        const int r = tid >> 3;
        const int cp = tid & 7;
        const float* ws = wT + (size_t)(ch * 32 + r) * 64 + cp * 8;
        unsigned dstB = bBase + (unsigned)(s * BBUF + r * BPITCH) * 4u + cp * 32u;
        cp_async16(dstB, ws, true);
        cp_async16(dstB + 16, ws + 4, true);
    };

    #pragma unroll
    for (int i = 0; i < STAGES - 1; i++) {
        if (i < KCH) prefetch(i);
        cp_commit();
    }

    for (int ch = 0; ch < KCH; ch++) {
        cp_wait<STAGES - 2>();
        __syncthreads();

        if (ch + STAGES - 1 < KCH) prefetch(ch + STAGES - 1);
        cp_commit();

        const int s = ch % STAGES;
        const float* A = smem + s * ABUF;
        const float* Bt = smem + STAGES * ABUF + s * BBUF;

        #pragma unroll
        for (int ks = 0; ks < 4; ks++) {
            const int k0 = ks * 8;
            uint32_t a[2][4];
            #pragma unroll
            for (int mt = 0; mt < 2; mt++) {
                const int m0 = warpM * 32 + mt * 16;
                a[mt][0] = __float_as_uint(A[(m0 + g) * APITCH + k0 + tg]);
                a[mt][1] = __float_as_uint(A[(m0 + g + 8) * APITCH + k0 + tg]);
                a[mt][2] = __float_as_uint(A[(m0 + g) * APITCH + k0 + tg + 4]);
                a[mt][3] = __float_as_uint(A[(m0 + g + 8) * APITCH + k0 + tg + 4]);
            }
            #pragma unroll
            for (int nt = 0; nt < 4; nt++) {
                const int n0 = warpN * 32 + nt * 8;
                uint32_t b0 = __float_as_uint(Bt[(k0 + tg) * BPITCH + n0 + g]);
                uint32_t b1 = __float_as_uint(Bt[(k0 + tg + 4) * BPITCH + n0 + g]);
                #pragma unroll
                for (int mt = 0; mt < 2; mt++)
                    mma_tf32(c[mt][nt], a[mt], b0, b1);
            }
        }
    }

    // ------------------------------- epilogue -------------------------------
    #pragma unroll
    for (int mt = 0; mt < 2; mt++) {
        #pragma unroll
        for (int rr = 0; rr < 2; rr++) {
            const int m = warpM * 32 + mt * 16 + rr * 8 + g;
            const int py = ybase + (m >> 5);
            const int px = x0 + (m & 31);
            const size_t pos = ((size_t)b * 96 + py) * 96 + px;
            #pragma unroll
            for (int nt = 0; nt < 4; nt++) {
                const int o = warpN * 32 + nt * 8 + tg * 2;
                float v0 = c[mt][nt][rr * 2 + 0];
                float v1 = c[mt][nt][rr * 2 + 1];
                if constexpr (MODE == 0) {
                    const float2 pb = *(const float2*)&posbias[(size_t)(py * 96 + px) * 64 + o];
                    v0 += pb.x; v1 += pb.y;
                    const float2 sc = *(const float2*)&bnsc[o];
                    const float2 shb = *(const float2*)&bnsh[o];
                    v0 = fmaxf(fmaf(v0, sc.x, shb.x), 0.0f);
                    v1 = fmaxf(fmaf(v1, sc.y, shb.y), 0.0f);
                    *(float2*)&out[pos * 64 + o] = make_float2(v0, v1);
                } else if constexpr (MODE == 1) {
                    if (o < 18)     out[pos * 18 + o]     = v0 + chbias[o];
                    if (o + 1 < 18) out[pos * 18 + o + 1] = v1 + chbias[o + 1];
                } else {
                    const float2 sc = *(const float2*)&bnsc[o];
                    const float2 shb = *(const float2*)&bnsh[o];
                    v0 = fmaxf(fmaf(v0, sc.x, shb.x), 0.0f);
                    v1 = fmaxf(fmaf(v1, sc.y, shb.y), 0.0f);
                    *(float2*)&out[pos * 64 + o] = make_float2(v0, v1);
                }
            }
        }
    }
}

// --------------------------- deform sampling -------------------------------
__device__ __forceinline__ void corner_acc(const float4* __restrict__ base,
                                           int yy, int xx, int cq, float w,
                                           float4& acc)
{
    if ((unsigned)yy < 96u && (unsigned)xx < 96u) {
        float4 vv = base[(yy * 96 + xx) * 16 + cq];
        acc.x = fmaf(w, vv.x, acc.x);
        acc.y = fmaf(w, vv.y, acc.y);
        acc.z = fmaf(w, vv.z, acc.z);
        acc.w = fmaf(w, vv.w, acc.w);
    }
}

__global__ void sample_kernel(const float* __restrict__ x1,
                              const float* __restrict__ offs,
                              float* __restrict__ samp)
{
    int gid = blockIdx.x * blockDim.x + threadIdx.x;   // kPos * 16
    if (gid >= sh::kPos * 16) return;
    const int cq = gid & 15;
    const int pos = gid >> 4;
    const int b = pos / (sh::kH * sh::kW);
    const int rem = pos % (sh::kH * sh::kW);
    const int y = rem / sh::kW, x = rem % sh::kW;

    const float* op = offs + (size_t)pos * 18;
    const float4* base = (const float4*)x1 + (size_t)(b * sh::kH * sh::kW) * 16;
    float4* outp = (float4*)(samp + (size_t)pos * 576);

    #pragma unroll
    for (int t = 0; t < 9; t++) {
        float oy = op[2 * t];
        float ox = op[2 * t + 1];
        float py = (float)(y + t / 3 - 1) + oy;
        float px = (float)(x + t % 3 - 1) + ox;
        float y0f = floorf(py), x0f = floorf(px);
        float fy = py - y0f, fx = px - x0f;
        int y0 = (int)y0f, xx0 = (int)x0f;
        float w00 = (1.0f - fy) * (1.0f - fx);
        float w01 = (1.0f - fy) * fx;
        float w10 = fy * (1.0f - fx);
        float w11 = fy * fx;
        float4 acc = make_float4(0.f, 0.f, 0.f, 0.f);
        corner_acc(base, y0,     xx0,     cq, w00, acc);
        corner_acc(base, y0,     xx0 + 1, cq, w01, acc);
        corner_acc(base, y0 + 1, xx0,     cq, w10, acc);
        corner_acc(base, y0 + 1, xx0 + 1, cq, w11, acc);
        outp[t * 16 + cq] = acc;
    }
}

// ------------------------------ final 1x1 ----------------------------------
__global__ void final_kernel(const float* __restrict__ x4,
                             const float* __restrict__ ow,
                             const float* __restrict__ ob,
                             float* __restrict__ out)
{
    int pos = blockIdx.x * blockDim.x + threadIdx.x;
    if (pos >= sh::kPos) return;
    const float4* xr = (const float4*)(x4 + (size_t)pos * 64);
    const float4* wr = (const float4*)ow;
    float acc = ob[0];
    #pragma unroll
    for (int q = 0; q < 16; q++) {
        float4 a = xr[q], w = wr[q];
        acc = fmaf(a.x, w.x, acc);
        acc = fmaf(a.y, w.y, acc);
        acc = fmaf(a.z, w.z, acc);
        acc = fmaf(a.w, w.w, acc);
    }
    out[pos] = 1.0f / (1.0f + expf(-acc));
}

// ------------------------------ launcher -----------------------------------
extern "C" void kernel_launch(void* const* d_in, const int* in_sizes, int n_in,
                              void* d_out, int out_size)
{
    const float* features = (const float*)d_in[0];
    const float* coord_w  = (const float*)d_in[1];
    const float* coord_b  = (const float*)d_in[2];
    const float* bn1g = (const float*)d_in[3];
    const float* bn1b = (const float*)d_in[4];
    const float* bn1m = (const float*)d_in[5];
    const float* bn1v = (const float*)d_in[6];
    const float* off_w = (const float*)d_in[7];
    const float* off_b = (const float*)d_in[8];
    const float* dc_w  = (const float*)d_in[9];
    const float* bn2g = (const float*)d_in[10];
    const float* bn2b = (const float*)d_in[11];
    const float* bn2m = (const float*)d_in[12];
    const float* bn2v = (const float*)d_in[13];
    const float* r1_w = (const float*)d_in[14];
    const float* bn3g = (const float*)d_in[15];
    const float* bn3b = (const float*)d_in[16];
    const float* bn3m = (const float*)d_in[17];
    const float* bn3v = (const float*)d_in[18];
    const float* r2_w = (const float*)d_in[19];
    const float* bn4g = (const float*)d_in[20];
    const float* bn4b = (const float*)d_in[21];
    const float* bn4m = (const float*)d_in[22];
    const float* bn4v = (const float*)d_in[23];
    const float* out_w = (const float*)d_in[24];
    const float* out_b = (const float*)d_in[25];

    float *p_buf0, *p_buf1, *p_off, *p_samp, *p_w1t, *p_cb, *p_wofft,
          *p_wdct, *p_wr1t, *p_wr2t, *p_bnsc, *p_bnsh;
    cudaGetSymbolAddress((void**)&p_buf0, g_buf0);
    cudaGetSymbolAddress((void**)&p_buf1, g_buf1);
    cudaGetSymbolAddress((void**)&p_off,  g_offb);
    cudaGetSymbolAddress((void**)&p_samp, g_samp);
    cudaGetSymbolAddress((void**)&p_w1t,  g_w1t);
    cudaGetSymbolAddress((void**)&p_cb,   g_cb);
    cudaGetSymbolAddress((void**)&p_wofft, g_wofft);
    cudaGetSymbolAddress((void**)&p_wdct, g_wdct);
    cudaGetSymbolAddress((void**)&p_wr1t, g_wr1t);
    cudaGetSymbolAddress((void**)&p_wr2t, g_wr2t);
    cudaGetSymbolAddress((void**)&p_bnsc, g_bnsc);
    cudaGetSymbolAddress((void**)&p_bnsh, g_bnsh);

    cudaFuncSetAttribute(conv_mma<256, 9, 0>,
                         cudaFuncAttributeMaxDynamicSharedMemorySize, SMEM_BYTES);
    cudaFuncSetAttribute(conv_mma<64, 9, 1>,
                         cudaFuncAttributeMaxDynamicSharedMemorySize, SMEM_BYTES);
    cudaFuncSetAttribute(conv_mma<576, 1, 2>,
                         cudaFuncAttributeMaxDynamicSharedMemorySize, SMEM_BYTES);
    cudaFuncSetAttribute(conv_mma<64, 9, 2>,
                         cudaFuncAttributeMaxDynamicSharedMemorySize, SMEM_BYTES);

    // 1. prep
    const int prep_total = 2304 * 64 + 96 * 96 * 64 + 4 * 576 * 64 + 512;
    prep_kernel<<<(prep_total + 255) / 256, 256>>>(
        coord_w, coord_b, off_w, dc_w, r1_w, r2_w,
        bn1g, bn1b, bn1m, bn1v, bn2g, bn2b, bn2m, bn2v,
        bn3g, bn3b, bn3m, bn3v, bn4g, bn4b, bn4m, bn4v);

    dim3 grid(3, 24, 8);   // 32 x-cols, 4 rows per block -> 128 positions

    // 2. coord conv (256->64) + coord bias + BN1 + ReLU -> buf0
    conv_mma<256, 9, 0><<<grid, 256, SMEM_BYTES>>>(
        features, p_w1t, p_cb, nullptr, p_bnsc + 0, p_bnsh + 0, p_buf0);

    // 3. offset conv (64->18, padded 64) + bias -> g_offb
    conv_mma<64, 9, 1><<<grid, 256, SMEM_BYTES>>>(
        p_buf0, p_wofft, nullptr, off_b, nullptr, nullptr, p_off);

    // 4. deform bilinear sampling -> g_samp
    sample_kernel<<<(sh::kPos * 16 + 255) / 256, 256>>>(p_buf0, p_off, p_samp);

    // 5. deform einsum (K=576) + BN2 + ReLU -> buf1
    conv_mma<576, 1, 2><<<grid, 256, SMEM_BYTES>>>(
        p_samp, p_wdct, nullptr, nullptr, p_bnsc + 64, p_bnsh + 64, p_buf1);

    // 6. r1 conv + BN3 + ReLU -> buf0
    conv_mma<64, 9, 2><<<grid, 256, SMEM_BYTES>>>(
        p_buf1, p_wr1t, nullptr, nullptr, p_bnsc + 128, p_bnsh + 128, p_buf0);

    // 7. r2 conv + BN4 + ReLU -> buf1
    conv_mma<64, 9, 2><<<grid, 256, SMEM_BYTES>>>(
        p_buf0, p_wr2t, nullptr, nullptr, p_bnsc + 192, p_bnsh + 192, p_buf1);

    // 8. 1x1 conv + sigmoid -> d_out
    final_kernel<<<(sh::kPos + 255) / 256, 256>>>(
        p_buf1, out_w, out_b, (float*)d_out);
}

// round 6
// speedup vs baseline: 4.9638x; 1.5851x over previous
#include <cuda_runtime.h>
#include <cuda_fp16.h>
#include <math.h>
#include <stdint.h>

// ---------------------------------------------------------------------------
// SpatialHead on sm_103a — fp16 mma (fp32 accum) + 4-stage cp.async GEMM.
// fp16 mantissa == tf32 mantissa (10 bits), so precision matches the tf32
// version; activations/weights/samples stored half, all accumulation fp32.
// ---------------------------------------------------------------------------

namespace sh {
constexpr int kB = 8, kH = 96, kW = 96;
constexpr int kPos = kB * kH * kW;          // 73728
constexpr float kEps = 1e-5f;
}

// ------------------------- scratch (__device__ globals) --------------------
__device__ __align__(16) __half g_feath[(size_t)sh::kPos * 256];  // features fp16
__device__ __align__(16) __half g_buf0h[sh::kPos * 64];
__device__ __align__(16) __half g_buf1h[sh::kPos * 64];
__device__ __align__(16) float  g_offb[sh::kPos * 18];            // offsets fp32
__device__ __align__(16) __half g_samph[(size_t)sh::kPos * 576];  // bilinear samples
__device__ __align__(16) __half g_w1h[64 * 2304];                 // coord conv [o][k]
__device__ __align__(16) __half g_woffh[64 * 576];                // offset conv padded [o][k]
__device__ __align__(16) __half g_wdch[64 * 576];
__device__ __align__(16) __half g_wr1h[64 * 576];
__device__ __align__(16) __half g_wr2h[64 * 576];
__device__ __align__(16) float  g_cb[sh::kH * sh::kW * 64];       // coord bias map fp32
__device__ float g_bnsc[4 * 64];
__device__ float g_bnsh[4 * 64];

// ------------------------------ helpers ------------------------------------
__device__ __forceinline__ unsigned smem_u32(const void* p) {
    unsigned a;
    asm("{ .reg .u64 t; cvta.to.shared.u64 t, %1; cvt.u32.u64 %0, t; }"
        : "=r"(a) : "l"(p));
    return a;
}
__device__ __forceinline__ void cp_async16(unsigned dst, const void* src, bool ok) {
    int sz = ok ? 16 : 0;
    asm volatile("cp.async.cg.shared.global [%0], [%1], 16, %2;\n"
                 :: "r"(dst), "l"(src), "r"(sz));
}
__device__ __forceinline__ void cp_commit() {
    asm volatile("cp.async.commit_group;\n");
}
template <int N>
__device__ __forceinline__ void cp_wait() {
    asm volatile("cp.async.wait_group %0;\n" :: "n"(N));
}
__device__ __forceinline__ void mma_f16(float c[4], const uint32_t a[4],
                                        uint32_t b0, uint32_t b1) {
    asm volatile(
        "mma.sync.aligned.m16n8k16.row.col.f32.f16.f16.f32 "
        "{%0,%1,%2,%3}, {%4,%5,%6,%7}, {%8,%9}, {%0,%1,%2,%3};\n"
        : "+f"(c[0]), "+f"(c[1]), "+f"(c[2]), "+f"(c[3])
        : "r"(a[0]), "r"(a[1]), "r"(a[2]), "r"(a[3]), "r"(b0), "r"(b1));
}

// ------------------------- features fp32 -> fp16 ----------------------------
__global__ void f2h_kernel(const float* __restrict__ src, __half* __restrict__ dst,
                           int n8)
{
    int i = blockIdx.x * blockDim.x + threadIdx.x;
    if (i >= n8) return;
    const float4* s = (const float4*)src + (size_t)i * 2;
    float4 v0 = s[0], v1 = s[1];
    __half2 h[4];
    h[0] = __floats2half2_rn(v0.x, v0.y);
    h[1] = __floats2half2_rn(v0.z, v0.w);
    h[2] = __floats2half2_rn(v1.x, v1.y);
    h[3] = __floats2half2_rn(v1.z, v1.w);
    *(uint4*)&dst[(size_t)i * 8] = *(uint4*)h;
}

// ------------------------------ prep kernel --------------------------------
__global__ void prep_kernel(
    const float* __restrict__ coord_w, const float* __restrict__ coord_b,
    const float* __restrict__ off_w, const float* __restrict__ dc_w,
    const float* __restrict__ r1_w, const float* __restrict__ r2_w,
    const float* __restrict__ bn1g, const float* __restrict__ bn1b,
    const float* __restrict__ bn1m, const float* __restrict__ bn1v,
    const float* __restrict__ bn2g, const float* __restrict__ bn2b,
    const float* __restrict__ bn2m, const float* __restrict__ bn2v,
    const float* __restrict__ bn3g, const float* __restrict__ bn3b,
    const float* __restrict__ bn3m, const float* __restrict__ bn3v,
    const float* __restrict__ bn4g, const float* __restrict__ bn4b,
    const float* __restrict__ bn4m, const float* __restrict__ bn4v)
{
    int idx = blockIdx.x * blockDim.x + threadIdx.x;
    const int N1 = 64 * 2304;            // g_w1h
    const int N2 = sh::kH * sh::kW * 64; // g_cb
    const int N3 = 64 * 576;             // each small weight

    if (idx < N1) {
        int o = idx / 2304, k = idx % 2304;
        int t = k >> 8, c = k & 255;
        g_w1h[idx] = __float2half(coord_w[(o * 258 + c) * 9 + t]);
        return;
    }
    idx -= N1;
    if (idx < N2) {
        int o = idx & 63, p = idx >> 6;
        int y = p / 96, x = p % 96;
        float acc = coord_b[o];
        #pragma unroll
        for (int t = 0; t < 9; t++) {
            int yy = y + t / 3 - 1, xx = x + t % 3 - 1;
            if ((unsigned)yy < 96u && (unsigned)xx < 96u) {
                float xv = fmaf((float)xx, 2.0f / 95.0f, -1.0f);
                float yv = fmaf((float)yy, 2.0f / 95.0f, -1.0f);
                acc = fmaf(coord_w[(o * 258 + 256) * 9 + t], xv, acc);
                acc = fmaf(coord_w[(o * 258 + 257) * 9 + t], yv, acc);
            }
        }
        g_cb[p * 64 + o] = acc;
        return;
    }
    idx -= N2;
    if (idx < N3) {
        int o = idx / 576, k = idx % 576;
        int t = k >> 6, c = k & 63;
        g_woffh[idx] = (o < 18) ? __float2half(off_w[(o * 64 + c) * 9 + t])
                                : __float2half(0.0f);
        return;
    }
    idx -= N3;
    if (idx < N3) {
        int o = idx / 576, k = idx % 576;
        int t = k >> 6, c = k & 63;
        g_wdch[idx] = __float2half(dc_w[(o * 64 + c) * 9 + t]);
        return;
    }
    idx -= N3;
    if (idx < N3) {
        int o = idx / 576, k = idx % 576;
        int t = k >> 6, c = k & 63;
        g_wr1h[idx] = __float2half(r1_w[(o * 64 + c) * 9 + t]);
        return;
    }
    idx -= N3;
    if (idx < N3) {
        int o = idx / 576, k = idx % 576;
        int t = k >> 6, c = k & 63;
        g_wr2h[idx] = __float2half(r2_w[(o * 64 + c) * 9 + t]);
        return;
    }
    idx -= N3;
    if (idx < 512) {
        int which = idx >> 7, r = idx & 127, o = r & 63;
        const float* gs; const float* bs; const float* ms; const float* vs;
        if (which == 0)      { gs = bn1g; bs = bn1b; ms = bn1m; vs = bn1v; }
        else if (which == 1) { gs = bn2g; bs = bn2b; ms = bn2m; vs = bn2v; }
        else if (which == 2) { gs = bn3g; bs = bn3b; ms = bn3m; vs = bn3v; }
        else                 { gs = bn4g; bs = bn4b; ms = bn4m; vs = bn4v; }
        float sc = gs[o] * rsqrtf(vs[o] + sh::kEps);
        if (r < 64) g_bnsc[which * 64 + o] = sc;
        else        g_bnsh[which * 64 + o] = bs[o] - ms[o] * sc;
    }
}

// --------------------------- conv GEMM (fp16 mma) ---------------------------
// Block: 256 positions (8 rows x 32 cols) x 64 cout, 256 threads (8 warps).
// Warp grid 4(M) x 2(N): warp tile m64 x n32 = 4x4 mma.m16n8k16 tiles.
// 4-stage cp.async, one __syncthreads per 32-k chunk (2 mma k-steps).
// smem: A [pos][k] half pitch 40; B [n][k] half pitch 40 (weights stored
// [o][k] in gmem so B rows stream contiguously; fragment LDS conflict-free).
// MODE 0: + per-position bias + BN + ReLU -> half out (coord conv)
// MODE 1: + channel bias, store 18 floats  (offset conv)
// MODE 2: + BN + ReLU -> half out          (deform / r1 / r2)
constexpr int STAGES = 4;
constexpr int PITCH = 40;                   // halves
constexpr int ABUF_H = 256 * PITCH;         // 10240 halves / stage
constexpr int BBUF_H = 64 * PITCH;          // 2560 halves / stage
constexpr int SMEM_BYTES = STAGES * (ABUF_H + BBUF_H) * 2;  // 102400

template <int CIN, int TAPS, int MODE>
__global__ void __launch_bounds__(256, 2)
conv_mma(const __half* __restrict__ in, const __half* __restrict__ wT,
         const float* __restrict__ posbias, const float* __restrict__ chbias,
         const float* __restrict__ bnsc, const float* __restrict__ bnsh,
         void* __restrict__ outv)
{
    constexpr int CPT = CIN / 32;
    constexpr int KCH = TAPS * CPT;
    constexpr int KTOT = TAPS * CIN;
    extern __shared__ __half smemh[];
    const unsigned aBase = smem_u32(smemh);
    const unsigned bBase = aBase + STAGES * ABUF_H * 2;

    const int tid = threadIdx.x;
    const int wid = tid >> 5;
    const int lane = tid & 31;
    const int warpM = wid & 3;           // m64 each
    const int warpN = wid >> 2;          // n32 each
    const int g = lane >> 2;             // 0..7
    const int tg = lane & 3;             // 0..3

    const int x0 = blockIdx.x * 32;
    const int ybase = blockIdx.y * 8;
    const int b = blockIdx.z;

    // fill mapping: A -> thread t covers position t (64 B = 4 x cp16);
    //               B -> thread t covers o = t>>2, quarter (t&3)
    const int fpy = tid >> 5, fpx = tid & 31;

    float c[4][4][4];
    #pragma unroll
    for (int mt = 0; mt < 4; mt++)
        #pragma unroll
        for (int nt = 0; nt < 4; nt++)
            #pragma unroll
            for (int r = 0; r < 4; r++) c[mt][nt][r] = 0.0f;

    auto prefetch = [&](int ch) {
        const int s = ch % STAGES;
        const int t = (TAPS == 1) ? 0 : (ch / CPT);
        const int c0 = (ch % CPT) * 32;
        const int dy = (TAPS == 1) ? 0 : (t / 3 - 1);
        const int dx = (TAPS == 1) ? 0 : (t % 3 - 1);
        // A: 256 pos x 32 halves
        const int yy = ybase + fpy + dy;
        const int xx = x0 + fpx + dx;
        const bool ok = (TAPS == 1) || ((unsigned)yy < 96u && (unsigned)xx < 96u);
        const __half* src = ok
            ? in + (size_t)((b * 96 + yy) * 96 + xx) * CIN + c0
            : in;
        unsigned dstA = aBase + (unsigned)(s * ABUF_H + tid * PITCH) * 2u;
        #pragma unroll
        for (int q = 0; q < 4; q++)
            cp_async16(dstA + q * 16, src + q * 8, ok);
        // B: 64 o x 32 halves
        const int o = tid >> 2;
        const int q = tid & 3;
        const __half* ws = wT + (size_t)o * KTOT + ch * 32 + q * 8;
        unsigned dstB = bBase + (unsigned)(s * BBUF_H + o * PITCH) * 2u + q * 16u;
        cp_async16(dstB, ws, true);
    };

    #pragma unroll
    for (int i = 0; i < STAGES - 1; i++) {
        prefetch(i);
        cp_commit();
    }

    for (int ch = 0; ch < KCH; ch++) {
        cp_wait<STAGES - 2>();
        __syncthreads();

        if (ch + STAGES - 1 < KCH) prefetch(ch + STAGES - 1);
        cp_commit();

        const int s = ch % STAGES;
        const __half* A = smemh + s * ABUF_H;
        const __half* Bt = smemh + STAGES * ABUF_H + s * BBUF_H;

        #pragma unroll
        for (int ks = 0; ks < 2; ks++) {
            const int k0 = ks * 16;
            uint32_t a[4][4];
            #pragma unroll
            for (int mt = 0; mt < 4; mt++) {
                const int m0 = warpM * 64 + mt * 16;
                const __half* ar = A + (m0 + g) * PITCH + k0 + 2 * tg;
                a[mt][0] = *(const uint32_t*)ar;
                a[mt][1] = *(const uint32_t*)(ar + 8 * PITCH);
                a[mt][2] = *(const uint32_t*)(ar + 8);
                a[mt][3] = *(const uint32_t*)(ar + 8 * PITCH + 8);
            }
            #pragma unroll
            for (int nt = 0; nt < 4; nt++) {
                const int n0 = warpN * 32 + nt * 8;
                const __half* br = Bt + (n0 + g) * PITCH + k0 + 2 * tg;
                uint32_t b0 = *(const uint32_t*)br;
                uint32_t b1 = *(const uint32_t*)(br + 8);
                #pragma unroll
                for (int mt = 0; mt < 4; mt++)
                    mma_f16(c[mt][nt], a[mt], b0, b1);
            }
        }
    }

    // ------------------------------- epilogue -------------------------------
    __half* outh = (__half*)outv;
    float* outf = (float*)outv;
    #pragma unroll
    for (int mt = 0; mt < 4; mt++) {
        #pragma unroll
        for (int rr = 0; rr < 2; rr++) {
            const int m = warpM * 64 + mt * 16 + rr * 8 + g;
            const int py = ybase + (m >> 5);
            const int px = x0 + (m & 31);
            const size_t pos = ((size_t)b * 96 + py) * 96 + px;
            #pragma unroll
            for (int nt = 0; nt < 4; nt++) {
                const int o = warpN * 32 + nt * 8 + tg * 2;
                float v0 = c[mt][nt][rr * 2 + 0];
                float v1 = c[mt][nt][rr * 2 + 1];
                if constexpr (MODE == 0) {
                    const float2 pb = *(const float2*)&posbias[(size_t)(py * 96 + px) * 64 + o];
                    v0 += pb.x; v1 += pb.y;
                    const float2 sc = *(const float2*)&bnsc[o];
                    const float2 shb = *(const float2*)&bnsh[o];
                    v0 = fmaxf(fmaf(v0, sc.x, shb.x), 0.0f);
                    v1 = fmaxf(fmaf(v1, sc.y, shb.y), 0.0f);
                    *(__half2*)&outh[pos * 64 + o] = __floats2half2_rn(v0, v1);
                } else if constexpr (MODE == 1) {
                    if (o < 18)     outf[pos * 18 + o]     = v0 + chbias[o];
                    if (o + 1 < 18) outf[pos * 18 + o + 1] = v1 + chbias[o + 1];
                } else {
                    const float2 sc = *(const float2*)&bnsc[o];
                    const float2 shb = *(const float2*)&bnsh[o];
                    v0 = fmaxf(fmaf(v0, sc.x, shb.x), 0.0f);
                    v1 = fmaxf(fmaf(v1, sc.y, shb.y), 0.0f);
                    *(__half2*)&outh[pos * 64 + o] = __floats2half2_rn(v0, v1);
                }
            }
        }
    }
}

// --------------------------- deform sampling (fp16) ------------------------
__device__ __forceinline__ void corner_acc_h(const uint4* __restrict__ base,
                                             int yy, int xx, int cq, float w,
                                             float2 acc[4])
{
    if ((unsigned)yy < 96u && (unsigned)xx < 96u) {
        uint4 v = base[(yy * 96 + xx) * 8 + cq];
        const __half2* hp = (const __half2*)&v;
        #pragma unroll
        for (int i = 0; i < 4; i++) {
            float2 f = __half22float2(hp[i]);
            acc[i].x = fmaf(w, f.x, acc[i].x);
            acc[i].y = fmaf(w, f.y, acc[i].y);
        }
    }
}

__global__ void sample_kernel(const __half* __restrict__ x1,
                              const float* __restrict__ offs,
                              __half* __restrict__ samp)
{
    int gid = blockIdx.x * blockDim.x + threadIdx.x;   // kPos * 8
    if (gid >= sh::kPos * 8) return;
    const int cq = gid & 7;                            // 8 channels each
    const int pos = gid >> 3;
    const int b = pos / (sh::kH * sh::kW);
    const int rem = pos % (sh::kH * sh::kW);
    const int y = rem / sh::kW, x = rem % sh::kW;

    const float* op = offs + (size_t)pos * 18;
    const uint4* base = (const uint4*)(x1 + (size_t)(b * sh::kH * sh::kW) * 64);
    uint4* outp = (uint4*)(samp + (size_t)pos * 576);

    #pragma unroll
    for (int t = 0; t < 9; t++) {
        float oy = op[2 * t];
        float ox = op[2 * t + 1];
        float py = (float)(y + t / 3 - 1) + oy;
        float px = (float)(x + t % 3 - 1) + ox;
        float y0f = floorf(py), x0f = floorf(px);
        float fy = py - y0f, fx = px - x0f;
        int y0 = (int)y0f, xx0 = (int)x0f;
        float w00 = (1.0f - fy) * (1.0f - fx);
        float w01 = (1.0f - fy) * fx;
        float w10 = fy * (1.0f - fx);
        float w11 = fy * fx;
        float2 acc[4] = {{0.f,0.f},{0.f,0.f},{0.f,0.f},{0.f,0.f}};
        corner_acc_h(base, y0,     xx0,     cq, w00, acc);
        corner_acc_h(base, y0,     xx0 + 1, cq, w01, acc);
        corner_acc_h(base, y0 + 1, xx0,     cq, w10, acc);
        corner_acc_h(base, y0 + 1, xx0 + 1, cq, w11, acc);
        __half2 r[4];
        #pragma unroll
        for (int i = 0; i < 4; i++) r[i] = __floats2half2_rn(acc[i].x, acc[i].y);
        outp[t * 8 + cq] = *(uint4*)r;
    }
}

// ------------------------------ final 1x1 ----------------------------------
__global__ void final_kernel(const __half* __restrict__ x4,
                             const float* __restrict__ ow,
                             const float* __restrict__ ob,
                             float* __restrict__ out)
{
    int pos = blockIdx.x * blockDim.x + threadIdx.x;
    if (pos >= sh::kPos) return;
    const uint4* xr = (const uint4*)(x4 + (size_t)pos * 64);
    float acc = ob[0];
    #pragma unroll
    for (int q = 0; q < 8; q++) {
        uint4 v = xr[q];
        const __half2* hp = (const __half2*)&v;
        #pragma unroll
        for (int i = 0; i < 4; i++) {
            float2 f = __half22float2(hp[i]);
            acc = fmaf(f.x, ow[q * 8 + i * 2 + 0], acc);
            acc = fmaf(f.y, ow[q * 8 + i * 2 + 1], acc);
        }
    }
    out[pos] = 1.0f / (1.0f + expf(-acc));
}

// ------------------------------ launcher -----------------------------------
extern "C" void kernel_launch(void* const* d_in, const int* in_sizes, int n_in,
                              void* d_out, int out_size)
{
    const float* features = (const float*)d_in[0];
    const float* coord_w  = (const float*)d_in[1];
    const float* coord_b  = (const float*)d_in[2];
    const float* bn1g = (const float*)d_in[3];
    const float* bn1b = (const float*)d_in[4];
    const float* bn1m = (const float*)d_in[5];
    const float* bn1v = (const float*)d_in[6];
    const float* off_w = (const float*)d_in[7];
    const float* off_b = (const float*)d_in[8];
    const float* dc_w  = (const float*)d_in[9];
    const float* bn2g = (const float*)d_in[10];
    const float* bn2b = (const float*)d_in[11];
    const float* bn2m = (const float*)d_in[12];
    const float* bn2v = (const float*)d_in[13];
    const float* r1_w = (const float*)d_in[14];
    const float* bn3g = (const float*)d_in[15];
    const float* bn3b = (const float*)d_in[16];
    const float* bn3m = (const float*)d_in[17];
    const float* bn3v = (const float*)d_in[18];
    const float* r2_w = (const float*)d_in[19];
    const float* bn4g = (const float*)d_in[20];
    const float* bn4b = (const float*)d_in[21];
    const float* bn4m = (const float*)d_in[22];
    const float* bn4v = (const float*)d_in[23];
    const float* out_w = (const float*)d_in[24];
    const float* out_b = (const float*)d_in[25];

    __half *p_feath, *p_buf0, *p_buf1, *p_samp, *p_w1h, *p_woffh, *p_wdch,
           *p_wr1h, *p_wr2h;
    float *p_off, *p_cb, *p_bnsc, *p_bnsh;
    cudaGetSymbolAddress((void**)&p_feath, g_feath);
    cudaGetSymbolAddress((void**)&p_buf0, g_buf0h);
    cudaGetSymbolAddress((void**)&p_buf1, g_buf1h);
    cudaGetSymbolAddress((void**)&p_off,  g_offb);
    cudaGetSymbolAddress((void**)&p_samp, g_samph);
    cudaGetSymbolAddress((void**)&p_w1h,  g_w1h);
    cudaGetSymbolAddress((void**)&p_woffh, g_woffh);
    cudaGetSymbolAddress((void**)&p_wdch, g_wdch);
    cudaGetSymbolAddress((void**)&p_wr1h, g_wr1h);
    cudaGetSymbolAddress((void**)&p_wr2h, g_wr2h);
    cudaGetSymbolAddress((void**)&p_cb,   g_cb);
    cudaGetSymbolAddress((void**)&p_bnsc, g_bnsc);
    cudaGetSymbolAddress((void**)&p_bnsh, g_bnsh);

    cudaFuncSetAttribute(conv_mma<256, 9, 0>,
                         cudaFuncAttributeMaxDynamicSharedMemorySize, SMEM_BYTES);
    cudaFuncSetAttribute(conv_mma<64, 9, 1>,
                         cudaFuncAttributeMaxDynamicSharedMemorySize, SMEM_BYTES);
    cudaFuncSetAttribute(conv_mma<576, 1, 2>,
                         cudaFuncAttributeMaxDynamicSharedMemorySize, SMEM_BYTES);
    cudaFuncSetAttribute(conv_mma<64, 9, 2>,
                         cudaFuncAttributeMaxDynamicSharedMemorySize, SMEM_BYTES);

    // 0. features -> fp16
    const int n8 = sh::kPos * 256 / 8;
    f2h_kernel<<<(n8 + 255) / 256, 256>>>(features, p_feath, n8);

    // 1. prep: weights -> [o][k] fp16, coord bias map, folded BN
    const int prep_total = 64 * 2304 + 96 * 96 * 64 + 4 * 64 * 576 + 512;
    prep_kernel<<<(prep_total + 255) / 256, 256>>>(
        coord_w, coord_b, off_w, dc_w, r1_w, r2_w,
        bn1g, bn1b, bn1m, bn1v, bn2g, bn2b, bn2m, bn2v,
        bn3g, bn3b, bn3m, bn3v, bn4g, bn4b, bn4m, bn4v);

    dim3 grid(3, 12, 8);   // 32 x-cols, 8 rows -> 256 positions per block

    // 2. coord conv (256->64) + coord bias + BN1 + ReLU -> buf0 (half)
    conv_mma<256, 9, 0><<<grid, 256, SMEM_BYTES>>>(
        p_feath, p_w1h, p_cb, nullptr, p_bnsc + 0, p_bnsh + 0, p_buf0);

    // 3. offset conv (64->18) + bias -> g_offb (float)
    conv_mma<64, 9, 1><<<grid, 256, SMEM_BYTES>>>(
        p_buf0, p_woffh, nullptr, off_b, nullptr, nullptr, p_off);

    // 4. deform bilinear sampling -> g_samph (half)
    sample_kernel<<<(sh::kPos * 8 + 255) / 256, 256>>>(p_buf0, p_off, p_samp);

    // 5. deform einsum (K=576) + BN2 + ReLU -> buf1
    conv_mma<576, 1, 2><<<grid, 256, SMEM_BYTES>>>(
        p_samp, p_wdch, nullptr, nullptr, p_bnsc + 64, p_bnsh + 64, p_buf1);

    // 6. r1 conv + BN3 + ReLU -> buf0
    conv_mma<64, 9, 2><<<grid, 256, SMEM_BYTES>>>(
        p_buf1, p_wr1h, nullptr, nullptr, p_bnsc + 128, p_bnsh + 128, p_buf0);

    // 7. r2 conv + BN4 + ReLU -> buf1
    conv_mma<64, 9, 2><<<grid, 256, SMEM_BYTES>>>(
        p_buf0, p_wr2h, nullptr, nullptr, p_bnsc + 192, p_bnsh + 192, p_buf1);

    // 8. 1x1 conv + sigmoid -> d_out (float)
    final_kernel<<<(sh::kPos + 255) / 256, 256>>>(
        p_buf1, out_w, out_b, (float*)d_out);
}

// round 7
// speedup vs baseline: 6.1846x; 1.2459x over previous
#include <cuda_runtime.h>
#include <cuda_fp16.h>
#include <math.h>
#include <stdint.h>

// ---------------------------------------------------------------------------
// SpatialHead on sm_103a — fp16 mma + ldmatrix + 4-stage cp.async, 3 CTAs/SM.
// ---------------------------------------------------------------------------

namespace sh {
constexpr int kB = 8, kH = 96, kW = 96;
constexpr int kPos = kB * kH * kW;          // 73728
constexpr float kEps = 1e-5f;
}

// ------------------------- scratch (__device__ globals) --------------------
__device__ __align__(16) __half g_feath[(size_t)sh::kPos * 256];
__device__ __align__(16) __half g_buf0h[sh::kPos * 64];
__device__ __align__(16) __half g_buf1h[sh::kPos * 64];
__device__ __align__(16) float  g_offb[sh::kPos * 18];
__device__ __align__(16) __half g_samph[(size_t)sh::kPos * 576];
__device__ __align__(16) __half g_w1h[64 * 2304];                 // [o][k]
__device__ __align__(16) __half g_woffh[64 * 576];
__device__ __align__(16) __half g_wdch[64 * 576];
__device__ __align__(16) __half g_wr1h[64 * 576];
__device__ __align__(16) __half g_wr2h[64 * 576];
__device__ __align__(16) float  g_cb[sh::kH * sh::kW * 64];
__device__ float g_bnsc[4 * 64];
__device__ float g_bnsh[4 * 64];

// ------------------------------ helpers ------------------------------------
__device__ __forceinline__ unsigned smem_u32(const void* p) {
    unsigned a;
    asm("{ .reg .u64 t; cvta.to.shared.u64 t, %1; cvt.u32.u64 %0, t; }"
        : "=r"(a) : "l"(p));
    return a;
}
__device__ __forceinline__ void cp_async16(unsigned dst, const void* src, bool ok) {
    int sz = ok ? 16 : 0;
    asm volatile("cp.async.cg.shared.global [%0], [%1], 16, %2;\n"
                 :: "r"(dst), "l"(src), "r"(sz));
}
__device__ __forceinline__ void cp_commit() {
    asm volatile("cp.async.commit_group;\n");
}
template <int N>
__device__ __forceinline__ void cp_wait() {
    asm volatile("cp.async.wait_group %0;\n" :: "n"(N));
}
__device__ __forceinline__ void ldsm_x4(uint32_t r[4], unsigned addr) {
    asm volatile("ldmatrix.sync.aligned.m8n8.x4.shared.b16 {%0,%1,%2,%3}, [%4];"
                 : "=r"(r[0]), "=r"(r[1]), "=r"(r[2]), "=r"(r[3]) : "r"(addr));
}
__device__ __forceinline__ void mma_f16(float c[4], const uint32_t a[4],
                                        uint32_t b0, uint32_t b1) {
    asm volatile(
        "mma.sync.aligned.m16n8k16.row.col.f32.f16.f16.f32 "
        "{%0,%1,%2,%3}, {%4,%5,%6,%7}, {%8,%9}, {%0,%1,%2,%3};\n"
        : "+f"(c[0]), "+f"(c[1]), "+f"(c[2]), "+f"(c[3])
        : "r"(a[0]), "r"(a[1]), "r"(a[2]), "r"(a[3]), "r"(b0), "r"(b1));
}

// ------------------------- features fp32 -> fp16 ----------------------------
__global__ void f2h_kernel(const float* __restrict__ src, __half* __restrict__ dst,
                           int n8)
{
    int i = blockIdx.x * blockDim.x + threadIdx.x;
    if (i >= n8) return;
    const float4* s = (const float4*)src + (size_t)i * 2;
    float4 v0 = s[0], v1 = s[1];
    __half2 h[4];
    h[0] = __floats2half2_rn(v0.x, v0.y);
    h[1] = __floats2half2_rn(v0.z, v0.w);
    h[2] = __floats2half2_rn(v1.x, v1.y);
    h[3] = __floats2half2_rn(v1.z, v1.w);
    *(uint4*)&dst[(size_t)i * 8] = *(uint4*)h;
}

// ------------------------------ prep kernel --------------------------------
__global__ void prep_kernel(
    const float* __restrict__ coord_w, const float* __restrict__ coord_b,
    const float* __restrict__ off_w, const float* __restrict__ dc_w,
    const float* __restrict__ r1_w, const float* __restrict__ r2_w,
    const float* __restrict__ bn1g, const float* __restrict__ bn1b,
    const float* __restrict__ bn1m, const float* __restrict__ bn1v,
    const float* __restrict__ bn2g, const float* __restrict__ bn2b,
    const float* __restrict__ bn2m, const float* __restrict__ bn2v,
    const float* __restrict__ bn3g, const float* __restrict__ bn3b,
    const float* __restrict__ bn3m, const float* __restrict__ bn3v,
    const float* __restrict__ bn4g, const float* __restrict__ bn4b,
    const float* __restrict__ bn4m, const float* __restrict__ bn4v)
{
    int idx = blockIdx.x * blockDim.x + threadIdx.x;
    const int N1 = 64 * 2304;
    const int N2 = sh::kH * sh::kW * 64;
    const int N3 = 64 * 576;

    if (idx < N1) {
        int o = idx / 2304, k = idx % 2304;
        int t = k >> 8, c = k & 255;
        g_w1h[idx] = __float2half(coord_w[(o * 258 + c) * 9 + t]);
        return;
    }
    idx -= N1;
    if (idx < N2) {
        int o = idx & 63, p = idx >> 6;
        int y = p / 96, x = p % 96;
        float acc = coord_b[o];
        #pragma unroll
        for (int t = 0; t < 9; t++) {
            int yy = y + t / 3 - 1, xx = x + t % 3 - 1;
            if ((unsigned)yy < 96u && (unsigned)xx < 96u) {
                float xv = fmaf((float)xx, 2.0f / 95.0f, -1.0f);
                float yv = fmaf((float)yy, 2.0f / 95.0f, -1.0f);
                acc = fmaf(coord_w[(o * 258 + 256) * 9 + t], xv, acc);
                acc = fmaf(coord_w[(o * 258 + 257) * 9 + t], yv, acc);
            }
        }
        g_cb[p * 64 + o] = acc;
        return;
    }
    idx -= N2;
    if (idx < N3) {
        int o = idx / 576, k = idx % 576;
        int t = k >> 6, c = k & 63;
        g_woffh[idx] = (o < 18) ? __float2half(off_w[(o * 64 + c) * 9 + t])
                                : __float2half(0.0f);
        return;
    }
    idx -= N3;
    if (idx < N3) {
        int o = idx / 576, k = idx % 576;
        int t = k >> 6, c = k & 63;
        g_wdch[idx] = __float2half(dc_w[(o * 64 + c) * 9 + t]);
        return;
    }
    idx -= N3;
    if (idx < N3) {
        int o = idx / 576, k = idx % 576;
        int t = k >> 6, c = k & 63;
        g_wr1h[idx] = __float2half(r1_w[(o * 64 + c) * 9 + t]);
        return;
    }
    idx -= N3;
    if (idx < N3) {
        int o = idx / 576, k = idx % 576;
        int t = k >> 6, c = k & 63;
        g_wr2h[idx] = __float2half(r2_w[(o * 64 + c) * 9 + t]);
        return;
    }
    idx -= N3;
    if (idx < 512) {
        int which = idx >> 7, r = idx & 127, o = r & 63;
        const float* gs; const float* bs; const float* ms; const float* vs;
        if (which == 0)      { gs = bn1g; bs = bn1b; ms = bn1m; vs = bn1v; }
        else if (which == 1) { gs = bn2g; bs = bn2b; ms = bn2m; vs = bn2v; }
        else if (which == 2) { gs = bn3g; bs = bn3b; ms = bn3m; vs = bn3v; }
        else                 { gs = bn4g; bs = bn4b; ms = bn4m; vs = bn4v; }
        float sc = gs[o] * rsqrtf(vs[o] + sh::kEps);
        if (r < 64) g_bnsc[which * 64 + o] = sc;
        else        g_bnsh[which * 64 + o] = bs[o] - ms[o] * sc;
    }
}

// --------------------------- conv GEMM (fp16 mma + ldmatrix) ---------------
// Block: 128 positions (4 rows x 32 cols) x 64 cout, 256 threads, 8 warps.
// Warp grid 4(M) x 2(N): warp tile m32 x n32 = 2x4 mma.m16n8k16 tiles.
// 4-stage cp.async; fragments loaded with ldmatrix.x4 (pitch 40h rows are
// conflict-free: 8 rows x 80B stride cover 8 distinct 16B slots mod 128B).
// 3 CTAs/SM (60KB smem, <=84 regs).
constexpr int STAGES = 4;
constexpr int PITCH = 40;                   // halves
constexpr int ABUF_H = 128 * PITCH;         // 5120 halves / stage
constexpr int BBUF_H = 64 * PITCH;          // 2560 halves / stage
constexpr int SMEM_BYTES = STAGES * (ABUF_H + BBUF_H) * 2;  // 61440

template <int CIN, int TAPS, int MODE>
__global__ void __launch_bounds__(256, 3)
conv_mma(const __half* __restrict__ in, const __half* __restrict__ wT,
         const float* __restrict__ posbias, const float* __restrict__ chbias,
         const float* __restrict__ bnsc, const float* __restrict__ bnsh,
         void* __restrict__ outv)
{
    constexpr int CPT = CIN / 32;
    constexpr int KCH = TAPS * CPT;
    constexpr int KTOT = TAPS * CIN;
    extern __shared__ __half smemh[];
    const unsigned aBase = smem_u32(smemh);
    const unsigned bBase = aBase + STAGES * ABUF_H * 2;

    const int tid = threadIdx.x;
    const int wid = tid >> 5;
    const int lane = tid & 31;
    const int warpM = wid & 3;           // m32 each
    const int warpN = wid >> 2;          // n32 each
    const int g = lane >> 2;             // 0..7
    const int tg = lane & 3;             // 0..3

    const int x0 = blockIdx.x * 32;
    const int ybase = blockIdx.y * 4;
    const int b = blockIdx.z;

    // ldmatrix lane offsets (in halves)
    const int lrow = lane & 7;
    const int lsel = lane >> 3;          // 0..3
    const int aoff = (warpM * 32 + lrow + ((lsel & 1) << 3)) * PITCH
                   + ((lsel >> 1) << 3);
    const int boff = (warpN * 32 + lrow + ((lsel >> 1) << 3)) * PITCH
                   + ((lsel & 1) << 3);

    // fill mapping
    const int fp = tid >> 1;                    // position 0..127
    const int fhalf = (tid & 1) * 16;           // half-row of 32 channels
    const int fpy = fp >> 5, fpx = fp & 31;

    float c[2][4][4];
    #pragma unroll
    for (int mt = 0; mt < 2; mt++)
        #pragma unroll
        for (int nt = 0; nt < 4; nt++)
            #pragma unroll
            for (int r = 0; r < 4; r++) c[mt][nt][r] = 0.0f;

    auto prefetch = [&](int ch) {
        const int s = ch % STAGES;
        const int t = (TAPS == 1) ? 0 : (ch / CPT);
        const int c0 = (ch % CPT) * 32;
        const int dy = (TAPS == 1) ? 0 : (t / 3 - 1);
        const int dx = (TAPS == 1) ? 0 : (t % 3 - 1);
        // A: 128 pos x 32 halves, 2 x cp16 per thread
        const int yy = ybase + fpy + dy;
        const int xx = x0 + fpx + dx;
        const bool ok = (TAPS == 1) || ((unsigned)yy < 96u && (unsigned)xx < 96u);
        const __half* src = ok
            ? in + (size_t)((b * 96 + yy) * 96 + xx) * CIN + c0 + fhalf
            : in;
        unsigned dstA = aBase + (unsigned)(s * ABUF_H + fp * PITCH + fhalf) * 2u;
        cp_async16(dstA, src, ok);
        cp_async16(dstA + 16, src + 8, ok);
        // B: 64 o x 32 halves, 1 x cp16 per thread
        const int o = tid >> 2;
        const int q = tid & 3;
        const __half* ws = wT + (size_t)o * KTOT + ch * 32 + q * 8;
        unsigned dstB = bBase + (unsigned)(s * BBUF_H + o * PITCH) * 2u + q * 16u;
        cp_async16(dstB, ws, true);
    };

    #pragma unroll
    for (int i = 0; i < STAGES - 1; i++) {
        prefetch(i);
        cp_commit();
    }

    for (int ch = 0; ch < KCH; ch++) {
        cp_wait<STAGES - 2>();
        __syncthreads();

        if (ch + STAGES - 1 < KCH) prefetch(ch + STAGES - 1);
        cp_commit();

        const int s = ch % STAGES;
        const unsigned aAddr = aBase + (unsigned)(s * ABUF_H + aoff) * 2u;
        const unsigned bAddr = bBase + (unsigned)(s * BBUF_H + boff) * 2u;

        #pragma unroll
        for (int ks = 0; ks < 2; ks++) {
            uint32_t a[2][4], bb[2][4];
            ldsm_x4(a[0], aAddr + ks * 32);
            ldsm_x4(a[1], aAddr + 16 * PITCH * 2 + ks * 32);
            ldsm_x4(bb[0], bAddr + ks * 32);
            ldsm_x4(bb[1], bAddr + 16 * PITCH * 2 + ks * 32);
            #pragma unroll
            for (int p = 0; p < 2; p++)
                #pragma unroll
                for (int q = 0; q < 2; q++) {
                    const int nt = p * 2 + q;
                    mma_f16(c[0][nt], a[0], bb[p][2 * q], bb[p][2 * q + 1]);
                    mma_f16(c[1][nt], a[1], bb[p][2 * q], bb[p][2 * q + 1]);
                }
        }
    }

    // ------------------------------- epilogue -------------------------------
    __half* outh = (__half*)outv;
    float* outf = (float*)outv;
    #pragma unroll
    for (int mt = 0; mt < 2; mt++) {
        #pragma unroll
        for (int rr = 0; rr < 2; rr++) {
            const int m = warpM * 32 + mt * 16 + rr * 8 + g;
            const int py = ybase + (m >> 5);
            const int px = x0 + (m & 31);
            const size_t pos = ((size_t)b * 96 + py) * 96 + px;
            #pragma unroll
            for (int nt = 0; nt < 4; nt++) {
                const int o = warpN * 32 + nt * 8 + tg * 2;
                float v0 = c[mt][nt][rr * 2 + 0];
                float v1 = c[mt][nt][rr * 2 + 1];
                if constexpr (MODE == 0) {
                    const float2 pb = *(const float2*)&posbias[(size_t)(py * 96 + px) * 64 + o];
                    v0 += pb.x; v1 += pb.y;
                    const float2 sc = *(const float2*)&bnsc[o];
                    const float2 shb = *(const float2*)&bnsh[o];
                    v0 = fmaxf(fmaf(v0, sc.x, shb.x), 0.0f);
                    v1 = fmaxf(fmaf(v1, sc.y, shb.y), 0.0f);
                    *(__half2*)&outh[pos * 64 + o] = __floats2half2_rn(v0, v1);
                } else if constexpr (MODE == 1) {
                    if (o < 18)     outf[pos * 18 + o]     = v0 + chbias[o];
                    if (o + 1 < 18) outf[pos * 18 + o + 1] = v1 + chbias[o + 1];
                } else {
                    const float2 sc = *(const float2*)&bnsc[o];
                    const float2 shb = *(const float2*)&bnsh[o];
                    v0 = fmaxf(fmaf(v0, sc.x, shb.x), 0.0f);
                    v1 = fmaxf(fmaf(v1, sc.y, shb.y), 0.0f);
                    *(__half2*)&outh[pos * 64 + o] = __floats2half2_rn(v0, v1);
                }
            }
        }
    }
}

// --------------------------- deform sampling (fp16) ------------------------
__device__ __forceinline__ void corner_acc_h(const uint4* __restrict__ base,
                                             int yy, int xx, int cq, float w,
                                             float2 acc[4])
{
    if ((unsigned)yy < 96u && (unsigned)xx < 96u) {
        uint4 v = base[(yy * 96 + xx) * 8 + cq];
        const __half2* hp = (const __half2*)&v;
        #pragma unroll
        for (int i = 0; i < 4; i++) {
            float2 f = __half22float2(hp[i]);
            acc[i].x = fmaf(w, f.x, acc[i].x);
            acc[i].y = fmaf(w, f.y, acc[i].y);
        }
    }
}

__global__ void sample_kernel(const __half* __restrict__ x1,
                              const float* __restrict__ offs,
                              __half* __restrict__ samp)
{
    int gid = blockIdx.x * blockDim.x + threadIdx.x;   // kPos * 8
    if (gid >= sh::kPos * 8) return;
    const int cq = gid & 7;
    const int pos = gid >> 3;
    const int b = pos / (sh::kH * sh::kW);
    const int rem = pos % (sh::kH * sh::kW);
    const int y = rem / sh::kW, x = rem % sh::kW;

    const float* op = offs + (size_t)pos * 18;
    const uint4* base = (const uint4*)(x1 + (size_t)(b * sh::kH * sh::kW) * 64);
    uint4* outp = (uint4*)(samp + (size_t)pos * 576);

    #pragma unroll
    for (int t = 0; t < 9; t++) {
        float oy = op[2 * t];
        float ox = op[2 * t + 1];
        float py = (float)(y + t / 3 - 1) + oy;
        float px = (float)(x + t % 3 - 1) + ox;
        float y0f = floorf(py), x0f = floorf(px);
        float fy = py - y0f, fx = px - x0f;
        int y0 = (int)y0f, xx0 = (int)x0f;
        float w00 = (1.0f - fy) * (1.0f - fx);
        float w01 = (1.0f - fy) * fx;
        float w10 = fy * (1.0f - fx);
        float w11 = fy * fx;
        float2 acc[4] = {{0.f,0.f},{0.f,0.f},{0.f,0.f},{0.f,0.f}};
        corner_acc_h(base, y0,     xx0,     cq, w00, acc);
        corner_acc_h(base, y0,     xx0 + 1, cq, w01, acc);
        corner_acc_h(base, y0 + 1, xx0,     cq, w10, acc);
        corner_acc_h(base, y0 + 1, xx0 + 1, cq, w11, acc);
        __half2 r[4];
        #pragma unroll
        for (int i = 0; i < 4; i++) r[i] = __floats2half2_rn(acc[i].x, acc[i].y);
        outp[t * 8 + cq] = *(uint4*)r;
    }
}

// ------------------------------ final 1x1 ----------------------------------
__global__ void final_kernel(const __half* __restrict__ x4,
                             const float* __restrict__ ow,
                             const float* __restrict__ ob,
                             float* __restrict__ out)
{
    int pos = blockIdx.x * blockDim.x + threadIdx.x;
    if (pos >= sh::kPos) return;
    const uint4* xr = (const uint4*)(x4 + (size_t)pos * 64);
    float acc = ob[0];
    #pragma unroll
    for (int q = 0; q < 8; q++) {
        uint4 v = xr[q];
        const __half2* hp = (const __half2*)&v;
        #pragma unroll
        for (int i = 0; i < 4; i++) {
            float2 f = __half22float2(hp[i]);
            acc = fmaf(f.x, ow[q * 8 + i * 2 + 0], acc);
            acc = fmaf(f.y, ow[q * 8 + i * 2 + 1], acc);
        }
    }
    out[pos] = 1.0f / (1.0f + expf(-acc));
}

// ------------------------------ launcher -----------------------------------
extern "C" void kernel_launch(void* const* d_in, const int* in_sizes, int n_in,
                              void* d_out, int out_size)
{
    const float* features = (const float*)d_in[0];
    const float* coord_w  = (const float*)d_in[1];
    const float* coord_b  = (const float*)d_in[2];
    const float* bn1g = (const float*)d_in[3];
    const float* bn1b = (const float*)d_in[4];
    const float* bn1m = (const float*)d_in[5];
    const float* bn1v = (const float*)d_in[6];
    const float* off_w = (const float*)d_in[7];
    const float* off_b = (const float*)d_in[8];
    const float* dc_w  = (const float*)d_in[9];
    const float* bn2g = (const float*)d_in[10];
    const float* bn2b = (const float*)d_in[11];
    const float* bn2m = (const float*)d_in[12];
    const float* bn2v = (const float*)d_in[13];
    const float* r1_w = (const float*)d_in[14];
    const float* bn3g = (const float*)d_in[15];
    const float* bn3b = (const float*)d_in[16];
    const float* bn3m = (const float*)d_in[17];
    const float* bn3v = (const float*)d_in[18];
    const float* r2_w = (const float*)d_in[19];
    const float* bn4g = (const float*)d_in[20];
    const float* bn4b = (const float*)d_in[21];
    const float* bn4m = (const float*)d_in[22];
    const float* bn4v = (const float*)d_in[23];
    const float* out_w = (const float*)d_in[24];
    const float* out_b = (const float*)d_in[25];

    __half *p_feath, *p_buf0, *p_buf1, *p_samp, *p_w1h, *p_woffh, *p_wdch,
           *p_wr1h, *p_wr2h;
    float *p_off, *p_cb, *p_bnsc, *p_bnsh;
    cudaGetSymbolAddress((void**)&p_feath, g_feath);
    cudaGetSymbolAddress((void**)&p_buf0, g_buf0h);
    cudaGetSymbolAddress((void**)&p_buf1, g_buf1h);
    cudaGetSymbolAddress((void**)&p_off,  g_offb);
    cudaGetSymbolAddress((void**)&p_samp, g_samph);
    cudaGetSymbolAddress((void**)&p_w1h,  g_w1h);
    cudaGetSymbolAddress((void**)&p_woffh, g_woffh);
    cudaGetSymbolAddress((void**)&p_wdch, g_wdch);
    cudaGetSymbolAddress((void**)&p_wr1h, g_wr1h);
    cudaGetSymbolAddress((void**)&p_wr2h, g_wr2h);
    cudaGetSymbolAddress((void**)&p_cb,   g_cb);
    cudaGetSymbolAddress((void**)&p_bnsc, g_bnsc);
    cudaGetSymbolAddress((void**)&p_bnsh, g_bnsh);

    cudaFuncSetAttribute(conv_mma<256, 9, 0>,
                         cudaFuncAttributeMaxDynamicSharedMemorySize, SMEM_BYTES);
    cudaFuncSetAttribute(conv_mma<64, 9, 1>,
                         cudaFuncAttributeMaxDynamicSharedMemorySize, SMEM_BYTES);
    cudaFuncSetAttribute(conv_mma<576, 1, 2>,
                         cudaFuncAttributeMaxDynamicSharedMemorySize, SMEM_BYTES);
    cudaFuncSetAttribute(conv_mma<64, 9, 2>,
                         cudaFuncAttributeMaxDynamicSharedMemorySize, SMEM_BYTES);

    // 0. features -> fp16
    const int n8 = sh::kPos * 256 / 8;
    f2h_kernel<<<(n8 + 255) / 256, 256>>>(features, p_feath, n8);

    // 1. prep
    const int prep_total = 64 * 2304 + 96 * 96 * 64 + 4 * 64 * 576 + 512;
    prep_kernel<<<(prep_total + 255) / 256, 256>>>(
        coord_w, coord_b, off_w, dc_w, r1_w, r2_w,
        bn1g, bn1b, bn1m, bn1v, bn2g, bn2b, bn2m, bn2v,
        bn3g, bn3b, bn3m, bn3v, bn4g, bn4b, bn4m, bn4v);

    dim3 grid(3, 24, 8);   // 32 x-cols, 4 rows -> 128 positions per block

    // 2. coord conv + coord bias + BN1 + ReLU -> buf0 (half)
    conv_mma<256, 9, 0><<<grid, 256, SMEM_BYTES>>>(
        p_feath, p_w1h, p_cb, nullptr, p_bnsc + 0, p_bnsh + 0, p_buf0);

    // 3. offset conv (64->18) + bias -> g_offb (float)
    conv_mma<64, 9, 1><<<grid, 256, SMEM_BYTES>>>(
        p_buf0, p_woffh, nullptr, off_b, nullptr, nullptr, p_off);

    // 4. deform bilinear sampling -> g_samph
    sample_kernel<<<(sh::kPos * 8 + 255) / 256, 256>>>(p_buf0, p_off, p_samp);

    // 5. deform einsum (K=576) + BN2 + ReLU -> buf1
    conv_mma<576, 1, 2><<<grid, 256, SMEM_BYTES>>>(
        p_samp, p_wdch, nullptr, nullptr, p_bnsc + 64, p_bnsh + 64, p_buf1);

    // 6. r1 conv + BN3 + ReLU -> buf0
    conv_mma<64, 9, 2><<<grid, 256, SMEM_BYTES>>>(
        p_buf1, p_wr1h, nullptr, nullptr, p_bnsc + 128, p_bnsh + 128, p_buf0);

    // 7. r2 conv + BN4 + ReLU -> buf1
    conv_mma<64, 9, 2><<<grid, 256, SMEM_BYTES>>>(
        p_buf0, p_wr2h, nullptr, nullptr, p_bnsc + 192, p_bnsh + 192, p_buf1);

    // 8. 1x1 conv + sigmoid -> d_out
    final_kernel<<<(sh::kPos + 255) / 256, 256>>>(
        p_buf1, out_w, out_b, (float*)d_out);
}